// round 1
// baseline (speedup 1.0000x reference)
#include <cuda_runtime.h>
#include <cuda_bf16.h>
#include <math.h>

#define D_MODEL 1024
#define D_FF    4096
#define N_EXP   8
#define TOPK    2
#define T_TOK   4096
#define CAP     4096   // per-expert capacity (worst case: all tokens)

// -------------------- scratch (static device globals; no allocs) -----------
__device__ int   g_counts[N_EXP];
__device__ int   g_token_list[N_EXP * CAP];     // token id per slot
__device__ int   g_pos[T_TOK * TOPK];           // slot position per (token,k)
__device__ float g_gate[T_TOK * TOPK];          // renormalized gate per (token,k)
__device__ float g_h[(size_t)N_EXP * CAP * D_FF];    // 536 MB
__device__ float g_y[(size_t)N_EXP * CAP * D_MODEL]; // 134 MB

// -------------------- kernel 0: zero counts --------------------------------
__global__ void zero_counts_kernel() {
    if (threadIdx.x < N_EXP) g_counts[threadIdx.x] = 0;
}

// -------------------- kernel 1: router -------------------------------------
// one warp per token: 8 dot products of length 1024, softmax, top-2, scatter
__global__ void router_kernel(const float* __restrict__ x,
                              const float* __restrict__ Wr,
                              const float* __restrict__ br) {
    int t = blockIdx.x * 8 + threadIdx.y;
    if (t >= T_TOK) return;
    int lane = threadIdx.x;

    float acc[N_EXP];
#pragma unroll
    for (int e = 0; e < N_EXP; e++) acc[e] = 0.f;

    const float* xr = x + (size_t)t * D_MODEL;
    for (int d = lane; d < D_MODEL; d += 32) {
        float xv = xr[d];
        const float* w = Wr + (size_t)d * N_EXP;
#pragma unroll
        for (int e = 0; e < N_EXP; e++) acc[e] += xv * w[e];
    }
#pragma unroll
    for (int off = 16; off > 0; off >>= 1) {
#pragma unroll
        for (int e = 0; e < N_EXP; e++)
            acc[e] += __shfl_down_sync(0xffffffffu, acc[e], off);
    }
    if (lane != 0) return;

    float logits[N_EXP];
    float mx = -1e30f;
#pragma unroll
    for (int e = 0; e < N_EXP; e++) {
        logits[e] = acc[e] + br[e];
        mx = fmaxf(mx, logits[e]);
    }
    float p[N_EXP], den = 0.f;
#pragma unroll
    for (int e = 0; e < N_EXP; e++) { p[e] = expf(logits[e] - mx); den += p[e]; }
#pragma unroll
    for (int e = 0; e < N_EXP; e++) p[e] /= den;

    // top-2 (ties -> lower index, matching jax.lax.top_k)
    int e0 = 0;
#pragma unroll
    for (int e = 1; e < N_EXP; e++) if (p[e] > p[e0]) e0 = e;
    int e1 = (e0 == 0) ? 1 : 0;
#pragma unroll
    for (int e = 0; e < N_EXP; e++) {
        if (e == e0) continue;
        if (p[e] > p[e1]) e1 = e;
    }
    float s = p[e0] + p[e1];
    float g0 = p[e0] / s, g1 = p[e1] / s;

    int i0 = atomicAdd(&g_counts[e0], 1);
    int i1 = atomicAdd(&g_counts[e1], 1);
    g_token_list[e0 * CAP + i0] = t;
    g_token_list[e1 * CAP + i1] = t;
    g_pos[t * 2 + 0] = e0 * CAP + i0;
    g_pos[t * 2 + 1] = e1 * CAP + i1;
    g_gate[t * 2 + 0] = g0;
    g_gate[t * 2 + 1] = g1;
}

// -------------------- kernel 2: GEMM1 + bias + ReLU ------------------------
// h[slot, 0:4096] = relu( x[token] @ W1[e] + b1[e] )
// tiles: BM=128, BN=128, BK=16, 256 threads, 8x8 per thread
__global__ __launch_bounds__(256)
void gemm1_kernel(const float* __restrict__ x,
                  const float* __restrict__ W1,
                  const float* __restrict__ b1) {
    const int e = blockIdx.z;
    const int count = g_counts[e];
    const int m0 = blockIdx.y * 128;
    if (m0 >= count) return;
    const int n0 = blockIdx.x * 128;

    const float* B = W1 + (size_t)e * D_MODEL * D_FF;

    __shared__ float As[16][132];
    __shared__ float Bs[16][128];

    const int tid = threadIdx.x;
    const int tx = tid % 16;      // col group
    const int ty = tid / 16;      // row group

    // A loader mapping: 512 float4 slots; this thread handles 2 (rows r, r+64)
    const int rowA = tid >> 2;          // 0..63
    const int c4   = tid & 3;           // which float4 in the 16-float row chunk

    int tok0 = -1, tok1 = -1;
    if (m0 + rowA < count)      tok0 = g_token_list[e * CAP + m0 + rowA];
    if (m0 + rowA + 64 < count) tok1 = g_token_list[e * CAP + m0 + rowA + 64];

    // B loader mapping: rows kB, kB+8 ; cols nB*4
    const int kB = tid >> 5;            // 0..7
    const int nB = tid & 31;            // 0..31

    float acc[8][8];
#pragma unroll
    for (int i = 0; i < 8; i++)
#pragma unroll
        for (int j = 0; j < 8; j++) acc[i][j] = 0.f;

    for (int k0 = 0; k0 < D_MODEL; k0 += 16) {
        float4 a0 = make_float4(0.f, 0.f, 0.f, 0.f);
        float4 a1 = make_float4(0.f, 0.f, 0.f, 0.f);
        if (tok0 >= 0) a0 = *(const float4*)(x + (size_t)tok0 * D_MODEL + k0 + c4 * 4);
        if (tok1 >= 0) a1 = *(const float4*)(x + (size_t)tok1 * D_MODEL + k0 + c4 * 4);
        As[c4 * 4 + 0][rowA] = a0.x;
        As[c4 * 4 + 1][rowA] = a0.y;
        As[c4 * 4 + 2][rowA] = a0.z;
        As[c4 * 4 + 3][rowA] = a0.w;
        As[c4 * 4 + 0][rowA + 64] = a1.x;
        As[c4 * 4 + 1][rowA + 64] = a1.y;
        As[c4 * 4 + 2][rowA + 64] = a1.z;
        As[c4 * 4 + 3][rowA + 64] = a1.w;

        *(float4*)&Bs[kB][nB * 4]     = *(const float4*)(B + (size_t)(k0 + kB) * D_FF + n0 + nB * 4);
        *(float4*)&Bs[kB + 8][nB * 4] = *(const float4*)(B + (size_t)(k0 + kB + 8) * D_FF + n0 + nB * 4);
        __syncthreads();

#pragma unroll
        for (int k = 0; k < 16; k++) {
            float ar[8], brg[8];
            float4 av0 = *(const float4*)&As[k][ty * 8];
            float4 av1 = *(const float4*)&As[k][ty * 8 + 4];
            float4 bv0 = *(const float4*)&Bs[k][tx * 8];
            float4 bv1 = *(const float4*)&Bs[k][tx * 8 + 4];
            ar[0]=av0.x; ar[1]=av0.y; ar[2]=av0.z; ar[3]=av0.w;
            ar[4]=av1.x; ar[5]=av1.y; ar[6]=av1.z; ar[7]=av1.w;
            brg[0]=bv0.x; brg[1]=bv0.y; brg[2]=bv0.z; brg[3]=bv0.w;
            brg[4]=bv1.x; brg[5]=bv1.y; brg[6]=bv1.z; brg[7]=bv1.w;
#pragma unroll
            for (int i = 0; i < 8; i++)
#pragma unroll
                for (int j = 0; j < 8; j++)
                    acc[i][j] = fmaf(ar[i], brg[j], acc[i][j]);
        }
        __syncthreads();
    }

    // epilogue: bias + relu, store valid rows
    float4 bv0 = *(const float4*)(b1 + (size_t)e * D_FF + n0 + tx * 8);
    float4 bv1 = *(const float4*)(b1 + (size_t)e * D_FF + n0 + tx * 8 + 4);
    float bias[8] = {bv0.x, bv0.y, bv0.z, bv0.w, bv1.x, bv1.y, bv1.z, bv1.w};

#pragma unroll
    for (int i = 0; i < 8; i++) {
        int row = m0 + ty * 8 + i;
        if (row >= count) continue;
        float* hp = g_h + ((size_t)e * CAP + row) * D_FF + n0 + tx * 8;
        float4 o0, o1;
        o0.x = fmaxf(acc[i][0] + bias[0], 0.f);
        o0.y = fmaxf(acc[i][1] + bias[1], 0.f);
        o0.z = fmaxf(acc[i][2] + bias[2], 0.f);
        o0.w = fmaxf(acc[i][3] + bias[3], 0.f);
        o1.x = fmaxf(acc[i][4] + bias[4], 0.f);
        o1.y = fmaxf(acc[i][5] + bias[5], 0.f);
        o1.z = fmaxf(acc[i][6] + bias[6], 0.f);
        o1.w = fmaxf(acc[i][7] + bias[7], 0.f);
        *(float4*)(hp)     = o0;
        *(float4*)(hp + 4) = o1;
    }
}

// -------------------- kernel 3: GEMM2 + bias -------------------------------
// y[slot, 0:1024] = h[slot] @ W2[e] + b2[e]
__global__ __launch_bounds__(256)
void gemm2_kernel(const float* __restrict__ W2,
                  const float* __restrict__ b2) {
    const int e = blockIdx.z;
    const int count = g_counts[e];
    const int m0 = blockIdx.y * 128;
    if (m0 >= count) return;
    const int n0 = blockIdx.x * 128;

    const float* A = g_h + (size_t)e * CAP * D_FF;
    const float* B = W2 + (size_t)e * D_FF * D_MODEL;

    __shared__ float As[16][132];
    __shared__ float Bs[16][128];

    const int tid = threadIdx.x;
    const int tx = tid % 16;
    const int ty = tid / 16;

    const int rowA = tid >> 2;
    const int c4   = tid & 3;
    const int kB = tid >> 5;
    const int nB = tid & 31;

    float acc[8][8];
#pragma unroll
    for (int i = 0; i < 8; i++)
#pragma unroll
        for (int j = 0; j < 8; j++) acc[i][j] = 0.f;

    for (int k0 = 0; k0 < D_FF; k0 += 16) {
        float4 a0 = *(const float4*)(A + (size_t)(m0 + rowA) * D_FF + k0 + c4 * 4);
        float4 a1 = *(const float4*)(A + (size_t)(m0 + rowA + 64) * D_FF + k0 + c4 * 4);
        As[c4 * 4 + 0][rowA] = a0.x;
        As[c4 * 4 + 1][rowA] = a0.y;
        As[c4 * 4 + 2][rowA] = a0.z;
        As[c4 * 4 + 3][rowA] = a0.w;
        As[c4 * 4 + 0][rowA + 64] = a1.x;
        As[c4 * 4 + 1][rowA + 64] = a1.y;
        As[c4 * 4 + 2][rowA + 64] = a1.z;
        As[c4 * 4 + 3][rowA + 64] = a1.w;

        *(float4*)&Bs[kB][nB * 4]     = *(const float4*)(B + (size_t)(k0 + kB) * D_MODEL + n0 + nB * 4);
        *(float4*)&Bs[kB + 8][nB * 4] = *(const float4*)(B + (size_t)(k0 + kB + 8) * D_MODEL + n0 + nB * 4);
        __syncthreads();

#pragma unroll
        for (int k = 0; k < 16; k++) {
            float ar[8], brg[8];
            float4 av0 = *(const float4*)&As[k][ty * 8];
            float4 av1 = *(const float4*)&As[k][ty * 8 + 4];
            float4 bv0 = *(const float4*)&Bs[k][tx * 8];
            float4 bv1 = *(const float4*)&Bs[k][tx * 8 + 4];
            ar[0]=av0.x; ar[1]=av0.y; ar[2]=av0.z; ar[3]=av0.w;
            ar[4]=av1.x; ar[5]=av1.y; ar[6]=av1.z; ar[7]=av1.w;
            brg[0]=bv0.x; brg[1]=bv0.y; brg[2]=bv0.z; brg[3]=bv0.w;
            brg[4]=bv1.x; brg[5]=bv1.y; brg[6]=bv1.z; brg[7]=bv1.w;
#pragma unroll
            for (int i = 0; i < 8; i++)
#pragma unroll
                for (int j = 0; j < 8; j++)
                    acc[i][j] = fmaf(ar[i], brg[j], acc[i][j]);
        }
        __syncthreads();
    }

    float4 bv0 = *(const float4*)(b2 + (size_t)e * D_MODEL + n0 + tx * 8);
    float4 bv1 = *(const float4*)(b2 + (size_t)e * D_MODEL + n0 + tx * 8 + 4);
    float bias[8] = {bv0.x, bv0.y, bv0.z, bv0.w, bv1.x, bv1.y, bv1.z, bv1.w};

#pragma unroll
    for (int i = 0; i < 8; i++) {
        int row = m0 + ty * 8 + i;
        if (row >= count) continue;
        float* yp = g_y + ((size_t)e * CAP + row) * D_MODEL + n0 + tx * 8;
        float4 o0, o1;
        o0.x = acc[i][0] + bias[0];
        o0.y = acc[i][1] + bias[1];
        o0.z = acc[i][2] + bias[2];
        o0.w = acc[i][3] + bias[3];
        o1.x = acc[i][4] + bias[4];
        o1.y = acc[i][5] + bias[5];
        o1.z = acc[i][6] + bias[6];
        o1.w = acc[i][7] + bias[7];
        *(float4*)(yp)     = o0;
        *(float4*)(yp + 4) = o1;
    }
}

// -------------------- kernel 4: combine ------------------------------------
// out[t] = g0 * y[pos0] + g1 * y[pos1]
__global__ void combine_kernel(float* __restrict__ out) {
    int idx = blockIdx.x * blockDim.x + threadIdx.x;   // float4 index
    int total = T_TOK * (D_MODEL / 4);
    if (idx >= total) return;
    int t  = idx >> 8;          // D_MODEL/4 = 256
    int d4 = idx & 255;

    float g0 = g_gate[t * 2 + 0];
    float g1 = g_gate[t * 2 + 1];
    int   p0 = g_pos[t * 2 + 0];
    int   p1 = g_pos[t * 2 + 1];

    float4 y0 = *(const float4*)(g_y + (size_t)p0 * D_MODEL + d4 * 4);
    float4 y1 = *(const float4*)(g_y + (size_t)p1 * D_MODEL + d4 * 4);
    float4 o;
    o.x = g0 * y0.x + g1 * y1.x;
    o.y = g0 * y0.y + g1 * y1.y;
    o.z = g0 * y0.z + g1 * y1.z;
    o.w = g0 * y0.w + g1 * y1.w;
    *(float4*)(out + (size_t)t * D_MODEL + d4 * 4) = o;
}

// -------------------- launch ------------------------------------------------
extern "C" void kernel_launch(void* const* d_in, const int* in_sizes, int n_in,
                              void* d_out, int out_size) {
    const float* x  = (const float*)d_in[0];
    const float* Wr = (const float*)d_in[1];
    const float* br = (const float*)d_in[2];
    const float* W1 = (const float*)d_in[3];
    const float* b1 = (const float*)d_in[4];
    const float* W2 = (const float*)d_in[5];
    const float* b2 = (const float*)d_in[6];
    float* out = (float*)d_out;

    zero_counts_kernel<<<1, 32>>>();

    dim3 rblk(32, 8);
    router_kernel<<<T_TOK / 8, rblk>>>(x, Wr, br);

    dim3 g1(D_FF / 128, CAP / 128, N_EXP);
    gemm1_kernel<<<g1, 256>>>(x, W1, b1);

    dim3 g2(D_MODEL / 128, CAP / 128, N_EXP);
    gemm2_kernel<<<g2, 256>>>(W2, b2);

    int total4 = T_TOK * (D_MODEL / 4);
    combine_kernel<<<(total4 + 255) / 256, 256>>>(out);
}

// round 3
// speedup vs baseline: 2.2823x; 2.2823x over previous
#include <cuda_runtime.h>
#include <cuda_bf16.h>
#include <cstdint>
#include <math.h>

#define D_MODEL 1024
#define D_FF    4096
#define N_EXP   8
#define T_TOK   4096
#define CAP     4096

// SMEM geometry (bytes), bf16 elements with padded rows for conflict-free ldmatrix
// A plane: 128 rows x 40 bf16 (32 data + 8 pad)  = 10240 B
// B plane: 32 rows  x 136 bf16 (128 data + 8 pad) = 8704 B
#define A_PLANE   10240
#define B_PLANE   8704
#define A_ROW_B   80      // bytes per A row
#define B_ROW_B   272     // bytes per B row
#define OFF_AHI   0
#define OFF_ALO   (OFF_AHI + A_PLANE)
#define OFF_BHI   (OFF_ALO + A_PLANE)
#define OFF_BLO   (OFF_BHI + B_PLANE)
#define STAGE_B   (OFF_BLO + B_PLANE)       // 37888
#define SMEM_TOTAL (2 * STAGE_B)            // 75776

// ---------------- scratch (device globals; zero-initialized) ----------------
__device__ int   g_counts[N_EXP];
__device__ int   g_token_list[N_EXP * CAP];
__device__ float g_gate_slot[N_EXP * CAP];
__device__ float g_h[(size_t)N_EXP * CAP * D_FF];   // rows >= count stay 0 forever

// ---------------- PTX helpers ------------------------------------------------
__device__ __forceinline__ uint32_t smem_u32(const void* p) {
    uint32_t a;
    asm("{ .reg .u64 t; cvta.to.shared.u64 t, %1; cvt.u32.u64 %0, t; }" : "=r"(a) : "l"(p));
    return a;
}
__device__ __forceinline__ void ldsm4(uint32_t* r, uint32_t addr) {
    asm volatile("ldmatrix.sync.aligned.m8n8.x4.shared.b16 {%0,%1,%2,%3}, [%4];"
                 : "=r"(r[0]), "=r"(r[1]), "=r"(r[2]), "=r"(r[3]) : "r"(addr));
}
__device__ __forceinline__ void ldsm4t(uint32_t* r, uint32_t addr) {
    asm volatile("ldmatrix.sync.aligned.m8n8.x4.trans.shared.b16 {%0,%1,%2,%3}, [%4];"
                 : "=r"(r[0]), "=r"(r[1]), "=r"(r[2]), "=r"(r[3]) : "r"(addr));
}
__device__ __forceinline__ void mma16816(float* c, const uint32_t* a, const uint32_t* b) {
    asm volatile(
        "mma.sync.aligned.m16n8k16.row.col.f32.bf16.bf16.f32 "
        "{%0,%1,%2,%3}, {%4,%5,%6,%7}, {%8,%9}, {%0,%1,%2,%3};"
        : "+f"(c[0]), "+f"(c[1]), "+f"(c[2]), "+f"(c[3])
        : "r"(a[0]), "r"(a[1]), "r"(a[2]), "r"(a[3]), "r"(b[0]), "r"(b[1]));
}

// fp32x4 -> (hi bf16x4, lo bf16x4) packed as uint2 each
__device__ __forceinline__ void cvt4(float4 v, uint2& H, uint2& L) {
    __nv_bfloat16 h0 = __float2bfloat16(v.x), h1 = __float2bfloat16(v.y);
    __nv_bfloat16 h2 = __float2bfloat16(v.z), h3 = __float2bfloat16(v.w);
    float r0 = v.x - __bfloat162float(h0), r1 = v.y - __bfloat162float(h1);
    float r2 = v.z - __bfloat162float(h2), r3 = v.w - __bfloat162float(h3);
    __nv_bfloat162 hh0 = __halves2bfloat162(h0, h1);
    __nv_bfloat162 hh1 = __halves2bfloat162(h2, h3);
    __nv_bfloat162 ll0 = __floats2bfloat162_rn(r0, r1);
    __nv_bfloat162 ll1 = __floats2bfloat162_rn(r2, r3);
    H = make_uint2(*(uint32_t*)&hh0, *(uint32_t*)&hh1);
    L = make_uint2(*(uint32_t*)&ll0, *(uint32_t*)&ll1);
}

// ---------------- small kernels -----------------------------------------------
__global__ void zero_counts_kernel() {
    if (threadIdx.x < N_EXP) g_counts[threadIdx.x] = 0;
}
__global__ void zero_out_kernel(float* __restrict__ out) {
    size_t i = (size_t)blockIdx.x * blockDim.x + threadIdx.x;
    ((float4*)out)[i] = make_float4(0.f, 0.f, 0.f, 0.f);
}

// ---------------- router -------------------------------------------------------
__global__ void router_kernel(const float* __restrict__ x,
                              const float* __restrict__ Wr,
                              const float* __restrict__ br) {
    int t = blockIdx.x * 8 + threadIdx.y;
    if (t >= T_TOK) return;
    int lane = threadIdx.x;

    float acc[N_EXP];
#pragma unroll
    for (int e = 0; e < N_EXP; e++) acc[e] = 0.f;
    const float* xr = x + (size_t)t * D_MODEL;
    for (int d = lane; d < D_MODEL; d += 32) {
        float xv = xr[d];
        const float* w = Wr + (size_t)d * N_EXP;
#pragma unroll
        for (int e = 0; e < N_EXP; e++) acc[e] += xv * w[e];
    }
#pragma unroll
    for (int off = 16; off > 0; off >>= 1)
#pragma unroll
        for (int e = 0; e < N_EXP; e++)
            acc[e] += __shfl_down_sync(0xffffffffu, acc[e], off);
    if (lane != 0) return;

    float p[N_EXP], mx = -1e30f, den = 0.f;
#pragma unroll
    for (int e = 0; e < N_EXP; e++) { p[e] = acc[e] + br[e]; mx = fmaxf(mx, p[e]); }
#pragma unroll
    for (int e = 0; e < N_EXP; e++) { p[e] = expf(p[e] - mx); den += p[e]; }
#pragma unroll
    for (int e = 0; e < N_EXP; e++) p[e] /= den;

    int e0 = 0;
#pragma unroll
    for (int e = 1; e < N_EXP; e++) if (p[e] > p[e0]) e0 = e;
    int e1 = (e0 == 0) ? 1 : 0;
#pragma unroll
    for (int e = 0; e < N_EXP; e++) { if (e == e0) continue; if (p[e] > p[e1]) e1 = e; }
    float s = p[e0] + p[e1];

    int i0 = atomicAdd(&g_counts[e0], 1);
    int i1 = atomicAdd(&g_counts[e1], 1);
    g_token_list[e0 * CAP + i0] = t;
    g_token_list[e1 * CAP + i1] = t;
    g_gate_slot[e0 * CAP + i0] = p[e0] / s;
    g_gate_slot[e1 * CAP + i1] = p[e1] / s;
}

// ---------------- shared device GEMM pieces ------------------------------------
// store staged regs to a stage's smem (with fp32->bf16 split)
__device__ __forceinline__ void r2s(char* smem, uint32_t soff,
                                    const float4* rA, const float4* rB,
                                    int ar, int ak, int bk, int bn4) {
#pragma unroll
    for (int p = 0; p < 4; p++) {
        uint2 H, L;
        cvt4(rA[p], H, L);
        uint32_t off = (uint32_t)(ar + 32 * p) * A_ROW_B + (uint32_t)ak * 8;
        *(uint2*)(smem + soff + OFF_AHI + off) = H;
        *(uint2*)(smem + soff + OFF_ALO + off) = L;
    }
#pragma unroll
    for (int p = 0; p < 4; p++) {
        uint2 H, L;
        cvt4(rB[p], H, L);
        uint32_t off = (uint32_t)(bk + 8 * p) * B_ROW_B + (uint32_t)bn4 * 8;
        *(uint2*)(smem + soff + OFF_BHI + off) = H;
        *(uint2*)(smem + soff + OFF_BLO + off) = L;
    }
}

// one BK=32 compute step on stage soff
__device__ __forceinline__ void compute_stage(uint32_t sb, uint32_t soff,
                                              int wm, int wn, int lane,
                                              float acc[2][8][4]) {
    const uint32_t lrow = lane & 15;
    const uint32_t lhi  = (lane >> 4) << 3;   // 0 or 8
#pragma unroll
    for (int ks = 0; ks < 2; ks++) {
        uint32_t a_h[2][4], a_l[2][4];
#pragma unroll
        for (int mt = 0; mt < 2; mt++) {
            uint32_t addr = sb + soff + OFF_AHI
                + (uint32_t)(wm * 32 + mt * 16 + lrow) * A_ROW_B
                + (ks * 16 + lhi) * 2;
            ldsm4(a_h[mt], addr);
            ldsm4(a_l[mt], addr + A_PLANE);
        }
        uint32_t b_h[8][2], b_l[8][2];
#pragma unroll
        for (int nt2 = 0; nt2 < 4; nt2++) {
            uint32_t addr = sb + soff + OFF_BHI
                + (uint32_t)(ks * 16 + lrow) * B_ROW_B
                + (uint32_t)(wn * 64 + nt2 * 16 + lhi) * 2;
            uint32_t t[4];
            ldsm4t(t, addr);
            b_h[nt2 * 2][0] = t[0]; b_h[nt2 * 2][1] = t[1];
            b_h[nt2 * 2 + 1][0] = t[2]; b_h[nt2 * 2 + 1][1] = t[3];
            ldsm4t(t, addr + B_PLANE);
            b_l[nt2 * 2][0] = t[0]; b_l[nt2 * 2][1] = t[1];
            b_l[nt2 * 2 + 1][0] = t[2]; b_l[nt2 * 2 + 1][1] = t[3];
        }
#pragma unroll
        for (int mt = 0; mt < 2; mt++)
#pragma unroll
            for (int nt = 0; nt < 8; nt++) {
                mma16816(acc[mt][nt], a_h[mt], b_h[nt]);
                mma16816(acc[mt][nt], a_h[mt], b_l[nt]);
                mma16816(acc[mt][nt], a_l[mt], b_h[nt]);
            }
    }
}

// ---------------- GEMM1: h = relu(x[gather] @ W1[e] + b1[e]) -------------------
__global__ __launch_bounds__(256)
void gemm1_mma(const float* __restrict__ x, const float* __restrict__ W1,
               const float* __restrict__ b1) {
    extern __shared__ char smem[];
    const int e = blockIdx.z;
    const int count = g_counts[e];
    const int m0 = blockIdx.y * 128;
    if (m0 >= count) return;
    const int n0 = blockIdx.x * 128;

    const int tid = threadIdx.x;
    const int lane = tid & 31, wid = tid >> 5;
    const int wm = wid & 3, wn = wid >> 2;
    const uint32_t sb = smem_u32(smem);

    // loader indices
    const int ar = tid >> 3, ak = tid & 7;     // A: rows ar+32p, float4 ak
    const int bk = tid >> 5, bn4 = tid & 31;   // B: rows bk+8p, float4 bn4

    // gathered A row pointers (4 rows per thread)
    const float* aptr[4];
#pragma unroll
    for (int p = 0; p < 4; p++) {
        int r = m0 + ar + 32 * p;
        aptr[p] = (r < count) ? x + (size_t)g_token_list[e * CAP + r] * D_MODEL : nullptr;
    }
    const float* Bg = W1 + (size_t)e * D_MODEL * D_FF;

    float acc[2][8][4];
#pragma unroll
    for (int mt = 0; mt < 2; mt++)
#pragma unroll
        for (int nt = 0; nt < 8; nt++)
#pragma unroll
            for (int q = 0; q < 4; q++) acc[mt][nt][q] = 0.f;

    float4 rA[4], rB[4];
    const float4 z4 = make_float4(0.f, 0.f, 0.f, 0.f);
    // prologue: chunk 0
#pragma unroll
    for (int p = 0; p < 4; p++)
        rA[p] = aptr[p] ? *(const float4*)(aptr[p] + ak * 4) : z4;
#pragma unroll
    for (int p = 0; p < 4; p++)
        rB[p] = *(const float4*)(Bg + (size_t)(bk + 8 * p) * D_FF + n0 + bn4 * 4);
    r2s(smem, 0, rA, rB, ar, ak, bk, bn4);
    __syncthreads();

    const int NCH = D_MODEL / 32;   // 32
#pragma unroll 1
    for (int i = 0; i < NCH; i++) {
        uint32_t cur = (i & 1) * STAGE_B;
        if (i + 1 < NCH) {
            int k0 = (i + 1) * 32;
#pragma unroll
            for (int p = 0; p < 4; p++)
                rA[p] = aptr[p] ? *(const float4*)(aptr[p] + k0 + ak * 4) : z4;
#pragma unroll
            for (int p = 0; p < 4; p++)
                rB[p] = *(const float4*)(Bg + (size_t)(k0 + bk + 8 * p) * D_FF + n0 + bn4 * 4);
        }
        compute_stage(sb, cur, wm, wn, lane, acc);
        if (i + 1 < NCH) {
            r2s(smem, ((i + 1) & 1) * STAGE_B, rA, rB, ar, ak, bk, bn4);
            __syncthreads();
        }
    }

    // epilogue: bias + relu -> g_h
    const int lrow = lane >> 2, lcol = (lane & 3) * 2;
    const float* b1e = b1 + (size_t)e * D_FF + n0 + wn * 64;
    float2 bias[8];
#pragma unroll
    for (int nt = 0; nt < 8; nt++) bias[nt] = *(const float2*)(b1e + nt * 8 + lcol);

#pragma unroll
    for (int mt = 0; mt < 2; mt++)
#pragma unroll
        for (int half = 0; half < 2; half++) {
            int r = m0 + wm * 32 + mt * 16 + lrow + half * 8;
            if (r >= count) continue;
            float* hp = g_h + ((size_t)e * CAP + r) * D_FF + n0 + wn * 64;
#pragma unroll
            for (int nt = 0; nt < 8; nt++) {
                float2 o;
                o.x = fmaxf(acc[mt][nt][half * 2 + 0] + bias[nt].x, 0.f);
                o.y = fmaxf(acc[mt][nt][half * 2 + 1] + bias[nt].y, 0.f);
                *(float2*)(hp + nt * 8 + lcol) = o;
            }
        }
}

// ---------------- GEMM2: out[tok] += gate * (h @ W2[e] + b2[e]) ----------------
__global__ __launch_bounds__(256)
void gemm2_mma(const float* __restrict__ W2, const float* __restrict__ b2,
               float* __restrict__ out) {
    extern __shared__ char smem[];
    const int e = blockIdx.z;
    const int count = g_counts[e];
    const int m0 = blockIdx.y * 128;
    if (m0 >= count) return;
    const int n0 = blockIdx.x * 128;

    const int tid = threadIdx.x;
    const int lane = tid & 31, wid = tid >> 5;
    const int wm = wid & 3, wn = wid >> 2;
    const uint32_t sb = smem_u32(smem);

    const int ar = tid >> 3, ak = tid & 7;
    const int bk = tid >> 5, bn4 = tid & 31;

    const float* aptr[4];
#pragma unroll
    for (int p = 0; p < 4; p++)
        aptr[p] = g_h + ((size_t)e * CAP + m0 + ar + 32 * p) * D_FF;  // rows>=count are zeros
    const float* Bg = W2 + (size_t)e * D_FF * D_MODEL;

    float acc[2][8][4];
#pragma unroll
    for (int mt = 0; mt < 2; mt++)
#pragma unroll
        for (int nt = 0; nt < 8; nt++)
#pragma unroll
            for (int q = 0; q < 4; q++) acc[mt][nt][q] = 0.f;

    float4 rA[4], rB[4];
#pragma unroll
    for (int p = 0; p < 4; p++)
        rA[p] = *(const float4*)(aptr[p] + ak * 4);
#pragma unroll
    for (int p = 0; p < 4; p++)
        rB[p] = *(const float4*)(Bg + (size_t)(bk + 8 * p) * D_MODEL + n0 + bn4 * 4);
    r2s(smem, 0, rA, rB, ar, ak, bk, bn4);
    __syncthreads();

    const int NCH = D_FF / 32;   // 128
#pragma unroll 1
    for (int i = 0; i < NCH; i++) {
        uint32_t cur = (i & 1) * STAGE_B;
        if (i + 1 < NCH) {
            int k0 = (i + 1) * 32;
#pragma unroll
            for (int p = 0; p < 4; p++)
                rA[p] = *(const float4*)(aptr[p] + k0 + ak * 4);
#pragma unroll
            for (int p = 0; p < 4; p++)
                rB[p] = *(const float4*)(Bg + (size_t)(k0 + bk + 8 * p) * D_MODEL + n0 + bn4 * 4);
        }
        compute_stage(sb, cur, wm, wn, lane, acc);
        if (i + 1 < NCH) {
            r2s(smem, ((i + 1) & 1) * STAGE_B, rA, rB, ar, ak, bk, bn4);
            __syncthreads();
        }
    }

    // epilogue: bias + gate, 2-way deterministic atomic combine
    const int lrow = lane >> 2, lcol = (lane & 3) * 2;
    const float* b2e = b2 + (size_t)e * D_MODEL + n0 + wn * 64;
    float2 bias[8];
#pragma unroll
    for (int nt = 0; nt < 8; nt++) bias[nt] = *(const float2*)(b2e + nt * 8 + lcol);

#pragma unroll
    for (int mt = 0; mt < 2; mt++)
#pragma unroll
        for (int half = 0; half < 2; half++) {
            int r = m0 + wm * 32 + mt * 16 + lrow + half * 8;
            if (r >= count) continue;
            int tok = g_token_list[e * CAP + r];
            float gate = g_gate_slot[e * CAP + r];
            float* op = out + (size_t)tok * D_MODEL + n0 + wn * 64;
#pragma unroll
            for (int nt = 0; nt < 8; nt++) {
                atomicAdd(op + nt * 8 + lcol + 0, (acc[mt][nt][half * 2 + 0] + bias[nt].x) * gate);
                atomicAdd(op + nt * 8 + lcol + 1, (acc[mt][nt][half * 2 + 1] + bias[nt].y) * gate);
            }
        }
}

// ---------------- launch --------------------------------------------------------
extern "C" void kernel_launch(void* const* d_in, const int* in_sizes, int n_in,
                              void* d_out, int out_size) {
    const float* x  = (const float*)d_in[0];
    const float* Wr = (const float*)d_in[1];
    const float* br = (const float*)d_in[2];
    const float* W1 = (const float*)d_in[3];
    const float* b1 = (const float*)d_in[4];
    const float* W2 = (const float*)d_in[5];
    const float* b2 = (const float*)d_in[6];
    float* out = (float*)d_out;

    cudaFuncSetAttribute(gemm1_mma, cudaFuncAttributeMaxDynamicSharedMemorySize, SMEM_TOTAL);
    cudaFuncSetAttribute(gemm2_mma, cudaFuncAttributeMaxDynamicSharedMemorySize, SMEM_TOTAL);

    zero_counts_kernel<<<1, 32>>>();
    zero_out_kernel<<<(T_TOK * D_MODEL / 4) / 256, 256>>>(out);

    dim3 rblk(32, 8);
    router_kernel<<<T_TOK / 8, rblk>>>(x, Wr, br);

    dim3 g1(D_FF / 128, CAP / 128, N_EXP);
    gemm1_mma<<<g1, 256, SMEM_TOTAL>>>(x, W1, b1);

    dim3 g2(D_MODEL / 128, CAP / 128, N_EXP);
    gemm2_mma<<<g2, 256, SMEM_TOTAL>>>(W2, b2, out);
}

// round 4
// speedup vs baseline: 2.8825x; 1.2630x over previous
#include <cuda_runtime.h>
#include <cuda_fp16.h>
#include <cstdint>
#include <math.h>

#define D_MODEL 1024
#define D_FF    4096
#define N_EXP   8
#define T_TOK   4096
#define CAP     4096

// SMEM stage geometry (bytes)
#define A_ROW_B  80                    // 32 fp16 (64B) + 16B pad
#define A_PLANE  (128 * A_ROW_B)       // 10240
#define B_ROW_B  272                   // 128 fp16 (256B) + 16B pad
#define B_PLANE  (32 * B_ROW_B)        // 8704
#define OFF_AH   0
#define OFF_AL   A_PLANE
#define OFF_B    (2 * A_PLANE)
#define STAGE_B  (2 * A_PLANE + B_PLANE)   // 29184
#define NSTAGE   4
#define HDR_OFF  (NSTAGE * STAGE_B)        // 116736
#define SMEM_TOTAL (HDR_OFF + 1024)        // 117760

// ---------------- scratch (device globals; zero-initialized) ----------------
__device__ int    g_counts[N_EXP];
__device__ int    g_token_list[N_EXP * CAP];
__device__ float  g_gate_slot[N_EXP * CAP];
__device__ __half g_xh[(size_t)T_TOK * D_MODEL];
__device__ __half g_xl[(size_t)T_TOK * D_MODEL];
__device__ __half g_w1[(size_t)N_EXP * D_MODEL * D_FF];
__device__ __half g_w2[(size_t)N_EXP * D_FF * D_MODEL];
__device__ __half g_hh[(size_t)N_EXP * CAP * D_FF];   // rows >= count stay 0
__device__ __half g_hl[(size_t)N_EXP * CAP * D_FF];

// ---------------- PTX helpers ------------------------------------------------
__device__ __forceinline__ uint32_t smem_u32(const void* p) {
    uint32_t a;
    asm("{ .reg .u64 t; cvta.to.shared.u64 t, %1; cvt.u32.u64 %0, t; }" : "=r"(a) : "l"(p));
    return a;
}
__device__ __forceinline__ void cp16(uint32_t dst, const void* src, int szr) {
    asm volatile("cp.async.cg.shared.global [%0], [%1], 16, %2;"
                 :: "r"(dst), "l"(src), "r"(szr) : "memory");
}
__device__ __forceinline__ void cp_commit() {
    asm volatile("cp.async.commit_group;" ::: "memory");
}
template <int N>
__device__ __forceinline__ void cp_wait() {
    asm volatile("cp.async.wait_group %0;" :: "n"(N) : "memory");
}
__device__ __forceinline__ void ldsm4(uint32_t* r, uint32_t addr) {
    asm volatile("ldmatrix.sync.aligned.m8n8.x4.shared.b16 {%0,%1,%2,%3}, [%4];"
                 : "=r"(r[0]), "=r"(r[1]), "=r"(r[2]), "=r"(r[3]) : "r"(addr));
}
__device__ __forceinline__ void ldsm4t(uint32_t* r, uint32_t addr) {
    asm volatile("ldmatrix.sync.aligned.m8n8.x4.trans.shared.b16 {%0,%1,%2,%3}, [%4];"
                 : "=r"(r[0]), "=r"(r[1]), "=r"(r[2]), "=r"(r[3]) : "r"(addr));
}
__device__ __forceinline__ void mma16816(float* c, const uint32_t* a, const uint32_t* b) {
    asm volatile(
        "mma.sync.aligned.m16n8k16.row.col.f32.f16.f16.f32 "
        "{%0,%1,%2,%3}, {%4,%5,%6,%7}, {%8,%9}, {%0,%1,%2,%3};"
        : "+f"(c[0]), "+f"(c[1]), "+f"(c[2]), "+f"(c[3])
        : "r"(a[0]), "r"(a[1]), "r"(a[2]), "r"(a[3]), "r"(b[0]), "r"(b[1]));
}

// ---------------- small kernels -----------------------------------------------
__global__ void zero_counts_kernel() {
    if (threadIdx.x < N_EXP) g_counts[threadIdx.x] = 0;
}
__global__ void zero_out_kernel(float* __restrict__ out) {
    size_t i = (size_t)blockIdx.x * blockDim.x + threadIdx.x;
    ((float4*)out)[i] = make_float4(0.f, 0.f, 0.f, 0.f);
}
// W -> fp16 single plane (4 elems per thread)
__global__ void cvt_w_kernel(const float* __restrict__ w, __half* __restrict__ dst, int n4) {
    int i = blockIdx.x * blockDim.x + threadIdx.x;
    if (i >= n4) return;
    float4 v = ((const float4*)w)[i];
    __half2 a = __floats2half2_rn(v.x, v.y);
    __half2 b = __floats2half2_rn(v.z, v.w);
    ((__half2*)dst)[2 * i]     = a;
    ((__half2*)dst)[2 * i + 1] = b;
}
// x -> fp16 hi/lo planes
__global__ void split_x_kernel(const float* __restrict__ x, int n4) {
    int i = blockIdx.x * blockDim.x + threadIdx.x;
    if (i >= n4) return;
    float4 v = ((const float4*)x)[i];
    __half h0 = __float2half(v.x), h1 = __float2half(v.y);
    __half h2 = __float2half(v.z), h3 = __float2half(v.w);
    __half l0 = __float2half(v.x - __half2float(h0));
    __half l1 = __float2half(v.y - __half2float(h1));
    __half l2 = __float2half(v.z - __half2float(h2));
    __half l3 = __float2half(v.w - __half2float(h3));
    ((__half2*)g_xh)[2 * i]     = __halves2half2(h0, h1);
    ((__half2*)g_xh)[2 * i + 1] = __halves2half2(h2, h3);
    ((__half2*)g_xl)[2 * i]     = __halves2half2(l0, l1);
    ((__half2*)g_xl)[2 * i + 1] = __halves2half2(l2, l3);
}

// ---------------- router -------------------------------------------------------
__global__ void router_kernel(const float* __restrict__ x,
                              const float* __restrict__ Wr,
                              const float* __restrict__ br) {
    int t = blockIdx.x * 8 + threadIdx.y;
    if (t >= T_TOK) return;
    int lane = threadIdx.x;

    float acc[N_EXP];
#pragma unroll
    for (int e = 0; e < N_EXP; e++) acc[e] = 0.f;
    const float* xr = x + (size_t)t * D_MODEL;
    for (int d = lane; d < D_MODEL; d += 32) {
        float xv = xr[d];
        const float* w = Wr + (size_t)d * N_EXP;
#pragma unroll
        for (int e = 0; e < N_EXP; e++) acc[e] += xv * w[e];
    }
#pragma unroll
    for (int off = 16; off > 0; off >>= 1)
#pragma unroll
        for (int e = 0; e < N_EXP; e++)
            acc[e] += __shfl_down_sync(0xffffffffu, acc[e], off);
    if (lane != 0) return;

    float p[N_EXP], mx = -1e30f, den = 0.f;
#pragma unroll
    for (int e = 0; e < N_EXP; e++) { p[e] = acc[e] + br[e]; mx = fmaxf(mx, p[e]); }
#pragma unroll
    for (int e = 0; e < N_EXP; e++) { p[e] = expf(p[e] - mx); den += p[e]; }
#pragma unroll
    for (int e = 0; e < N_EXP; e++) p[e] /= den;

    int e0 = 0;
#pragma unroll
    for (int e = 1; e < N_EXP; e++) if (p[e] > p[e0]) e0 = e;
    int e1 = (e0 == 0) ? 1 : 0;
#pragma unroll
    for (int e = 0; e < N_EXP; e++) { if (e == e0) continue; if (p[e] > p[e1]) e1 = e; }
    float s = p[e0] + p[e1];

    int i0 = atomicAdd(&g_counts[e0], 1);
    int i1 = atomicAdd(&g_counts[e1], 1);
    g_token_list[e0 * CAP + i0] = t;
    g_token_list[e1 * CAP + i1] = t;
    g_gate_slot[e0 * CAP + i0] = p[e0] / s;
    g_gate_slot[e1 * CAP + i1] = p[e1] / s;
}

// ---------------- GEMM compute step (BK=32, 2 fp16 terms) ----------------------
__device__ __forceinline__ void compute_stage(uint32_t sb, uint32_t soff,
                                              int wm, int wn, int lane,
                                              float acc[2][4][4]) {
    const uint32_t lrow = lane & 15;
    const uint32_t lhi  = (lane >> 4) << 3;
#pragma unroll
    for (int ks = 0; ks < 2; ks++) {
        uint32_t a_h[2][4], a_l[2][4];
#pragma unroll
        for (int mt = 0; mt < 2; mt++) {
            uint32_t addr = sb + soff + OFF_AH
                + (uint32_t)(wm * 32 + mt * 16 + lrow) * A_ROW_B
                + (ks * 16 + lhi) * 2;
            ldsm4(a_h[mt], addr);
            ldsm4(a_l[mt], addr + A_PLANE);
        }
        uint32_t b[4][2];
#pragma unroll
        for (int nt2 = 0; nt2 < 2; nt2++) {
            uint32_t addr = sb + soff + OFF_B
                + (uint32_t)(ks * 16 + lrow) * B_ROW_B
                + (uint32_t)(wn * 32 + nt2 * 16 + lhi) * 2;
            uint32_t t[4];
            ldsm4t(t, addr);
            b[nt2 * 2][0] = t[0];     b[nt2 * 2][1] = t[1];
            b[nt2 * 2 + 1][0] = t[2]; b[nt2 * 2 + 1][1] = t[3];
        }
#pragma unroll
        for (int mt = 0; mt < 2; mt++)
#pragma unroll
            for (int nt = 0; nt < 4; nt++) {
                mma16816(acc[mt][nt], a_h[mt], b[nt]);
                mma16816(acc[mt][nt], a_l[mt], b[nt]);
            }
    }
}

// ---------------- GEMM1: h = relu(x[gather] @ W1[e] + b1[e]) -------------------
__global__ __launch_bounds__(512)
void gemm1_mma(const float* __restrict__ b1) {
    extern __shared__ char smem[];
    const int e = blockIdx.z;
    const int count = g_counts[e];
    const int m0 = blockIdx.y * 128;
    if (m0 >= count) return;
    const int n0 = blockIdx.x * 128;

    const int tid = threadIdx.x;
    const int lane = tid & 31, wid = tid >> 5;
    const int wm = wid & 3, wn = wid >> 2;
    const uint32_t sb = smem_u32(smem);

    int* stok = (int*)(smem + HDR_OFF);
    int* ssz  = (int*)(smem + HDR_OFF + 512);
    if (tid < 128) {
        int r = m0 + tid;
        bool v = r < count;
        stok[tid] = v ? g_token_list[e * CAP + r] : 0;
        ssz[tid]  = v ? 16 : 0;
    }
    __syncthreads();

    const __half* Bg = g_w1 + (size_t)e * D_MODEL * D_FF;

    // loader lambda-ish
    auto issue_loads = [&](int stage, int k0) {
#pragma unroll
        for (int h2 = 0; h2 < 2; h2++) {
            int idx = tid + h2 * 512;
            int plane = idx >> 9;
            int row = (idx >> 2) & 127;
            int c4 = idx & 3;
            uint32_t dst = sb + stage * STAGE_B + plane * A_PLANE
                         + (uint32_t)row * A_ROW_B + c4 * 16;
            const __half* base = plane ? g_xl : g_xh;
            const __half* src = base + (size_t)stok[row] * D_MODEL + k0 + c4 * 8;
            cp16(dst, src, ssz[row]);
        }
        {
            int row = tid >> 4, c16 = tid & 15;
            uint32_t dst = sb + stage * STAGE_B + OFF_B
                         + (uint32_t)row * B_ROW_B + c16 * 16;
            cp16(dst, Bg + (size_t)(k0 + row) * D_FF + n0 + c16 * 8, 16);
        }
        cp_commit();
    };

    float acc[2][4][4];
#pragma unroll
    for (int mt = 0; mt < 2; mt++)
#pragma unroll
        for (int nt = 0; nt < 4; nt++)
#pragma unroll
            for (int q = 0; q < 4; q++) acc[mt][nt][q] = 0.f;

    const int NCH = D_MODEL / 32;  // 32
    issue_loads(0, 0);
    issue_loads(1, 32);
    issue_loads(2, 64);

#pragma unroll 1
    for (int i = 0; i < NCH; i++) {
        cp_wait<2>();
        __syncthreads();
        if (i + 3 < NCH) issue_loads((i + 3) & 3, (i + 3) * 32);
        else cp_commit();
        compute_stage(sb, (i & 3) * STAGE_B, wm, wn, lane, acc);
    }

    // epilogue: bias + relu -> fp16 hi/lo planes
    const int lrow = lane >> 2, lcol = (lane & 3) * 2;
    const float* b1e = b1 + (size_t)e * D_FF + n0 + wn * 32;
    float2 bias[4];
#pragma unroll
    for (int nt = 0; nt < 4; nt++) bias[nt] = *(const float2*)(b1e + nt * 8 + lcol);

#pragma unroll
    for (int mt = 0; mt < 2; mt++)
#pragma unroll
        for (int half = 0; half < 2; half++) {
            int r = m0 + wm * 32 + mt * 16 + lrow + half * 8;
            if (r >= count) continue;
            size_t base = ((size_t)e * CAP + r) * D_FF + n0 + wn * 32;
#pragma unroll
            for (int nt = 0; nt < 4; nt++) {
                float v0 = fmaxf(acc[mt][nt][half * 2 + 0] + bias[nt].x, 0.f);
                float v1 = fmaxf(acc[mt][nt][half * 2 + 1] + bias[nt].y, 0.f);
                __half h0 = __float2half(v0), h1 = __float2half(v1);
                __half l0 = __float2half(v0 - __half2float(h0));
                __half l1 = __float2half(v1 - __half2float(h1));
                *(__half2*)(g_hh + base + nt * 8 + lcol) = __halves2half2(h0, h1);
                *(__half2*)(g_hl + base + nt * 8 + lcol) = __halves2half2(l0, l1);
            }
        }
}

// ---------------- GEMM2: out[tok] += gate * (h @ W2[e] + b2[e]) ----------------
__global__ __launch_bounds__(512)
void gemm2_mma(const float* __restrict__ b2, float* __restrict__ out) {
    extern __shared__ char smem[];
    const int e = blockIdx.z;
    const int count = g_counts[e];
    const int m0 = blockIdx.y * 128;
    if (m0 >= count) return;
    const int n0 = blockIdx.x * 128;

    const int tid = threadIdx.x;
    const int lane = tid & 31, wid = tid >> 5;
    const int wm = wid & 3, wn = wid >> 2;
    const uint32_t sb = smem_u32(smem);

    const __half* Bg = g_w2 + (size_t)e * D_FF * D_MODEL;
    const size_t arow0 = ((size_t)e * CAP + m0) * D_FF;

    auto issue_loads = [&](int stage, int k0) {
#pragma unroll
        for (int h2 = 0; h2 < 2; h2++) {
            int idx = tid + h2 * 512;
            int plane = idx >> 9;
            int row = (idx >> 2) & 127;
            int c4 = idx & 3;
            uint32_t dst = sb + stage * STAGE_B + plane * A_PLANE
                         + (uint32_t)row * A_ROW_B + c4 * 16;
            const __half* base = plane ? g_hl : g_hh;
            const __half* src = base + arow0 + (size_t)row * D_FF + k0 + c4 * 8;
            cp16(dst, src, 16);
        }
        {
            int row = tid >> 4, c16 = tid & 15;
            uint32_t dst = sb + stage * STAGE_B + OFF_B
                         + (uint32_t)row * B_ROW_B + c16 * 16;
            cp16(dst, Bg + (size_t)(k0 + row) * D_MODEL + n0 + c16 * 8, 16);
        }
        cp_commit();
    };

    float acc[2][4][4];
#pragma unroll
    for (int mt = 0; mt < 2; mt++)
#pragma unroll
        for (int nt = 0; nt < 4; nt++)
#pragma unroll
            for (int q = 0; q < 4; q++) acc[mt][nt][q] = 0.f;

    const int NCH = D_FF / 32;  // 128
    issue_loads(0, 0);
    issue_loads(1, 32);
    issue_loads(2, 64);

#pragma unroll 1
    for (int i = 0; i < NCH; i++) {
        cp_wait<2>();
        __syncthreads();
        if (i + 3 < NCH) issue_loads((i + 3) & 3, (i + 3) * 32);
        else cp_commit();
        compute_stage(sb, (i & 3) * STAGE_B, wm, wn, lane, acc);
    }

    // epilogue: bias + gate, 2-way deterministic atomic combine
    const int lrow = lane >> 2, lcol = (lane & 3) * 2;
    const float* b2e = b2 + (size_t)e * D_MODEL + n0 + wn * 32;
    float2 bias[4];
#pragma unroll
    for (int nt = 0; nt < 4; nt++) bias[nt] = *(const float2*)(b2e + nt * 8 + lcol);

#pragma unroll
    for (int mt = 0; mt < 2; mt++)
#pragma unroll
        for (int half = 0; half < 2; half++) {
            int r = m0 + wm * 32 + mt * 16 + lrow + half * 8;
            if (r >= count) continue;
            int tok = g_token_list[e * CAP + r];
            float gate = g_gate_slot[e * CAP + r];
            float* op = out + (size_t)tok * D_MODEL + n0 + wn * 32;
#pragma unroll
            for (int nt = 0; nt < 4; nt++) {
                atomicAdd(op + nt * 8 + lcol + 0, (acc[mt][nt][half * 2 + 0] + bias[nt].x) * gate);
                atomicAdd(op + nt * 8 + lcol + 1, (acc[mt][nt][half * 2 + 1] + bias[nt].y) * gate);
            }
        }
}

// ---------------- launch --------------------------------------------------------
extern "C" void kernel_launch(void* const* d_in, const int* in_sizes, int n_in,
                              void* d_out, int out_size) {
    const float* x  = (const float*)d_in[0];
    const float* Wr = (const float*)d_in[1];
    const float* br = (const float*)d_in[2];
    const float* W1 = (const float*)d_in[3];
    const float* b1 = (const float*)d_in[4];
    const float* W2 = (const float*)d_in[5];
    const float* b2 = (const float*)d_in[6];
    float* out = (float*)d_out;

    cudaFuncSetAttribute(gemm1_mma, cudaFuncAttributeMaxDynamicSharedMemorySize, SMEM_TOTAL);
    cudaFuncSetAttribute(gemm2_mma, cudaFuncAttributeMaxDynamicSharedMemorySize, SMEM_TOTAL);

    zero_counts_kernel<<<1, 32>>>();
    zero_out_kernel<<<(T_TOK * D_MODEL / 4) / 256, 256>>>(out);

    dim3 rblk(32, 8);
    router_kernel<<<T_TOK / 8, rblk>>>(x, Wr, br);

    {   // weight + x conversion
        __half* w1d; __half* w2d;
        cudaGetSymbolAddress((void**)&w1d, g_w1);
        cudaGetSymbolAddress((void**)&w2d, g_w2);
        int n4w = (N_EXP * D_MODEL * D_FF) / 4;           // 8.4M
        cvt_w_kernel<<<(n4w + 255) / 256, 256>>>(W1, w1d, n4w);
        cvt_w_kernel<<<(n4w + 255) / 256, 256>>>(W2, w2d, n4w);
        int n4x = (T_TOK * D_MODEL) / 4;
        split_x_kernel<<<(n4x + 255) / 256, 256>>>(x, n4x);
    }

    dim3 g1(D_FF / 128, CAP / 128, N_EXP);
    gemm1_mma<<<g1, 512, SMEM_TOTAL>>>(b1);

    dim3 g2(D_MODEL / 128, CAP / 128, N_EXP);
    gemm2_mma<<<g2, 512, SMEM_TOTAL>>>(b2, out);
}

// round 5
// speedup vs baseline: 4.9858x; 1.7297x over previous
#include <cuda_runtime.h>
#include <cuda_fp16.h>
#include <cstdint>
#include <math.h>

#define D_MODEL 1024
#define D_FF    4096
#define N_EXP   8
#define T_TOK   4096
#define CAP     4096

// SMEM stage geometry (bytes)
#define A_ROW_B  80                        // 32 fp16 (64B) + 16B pad
#define A_PLANE  (128 * A_ROW_B)           // 10240
#define B_ROW_B  528                       // 256 fp16 (512B) + 16B pad
#define B_PLANE  (32 * B_ROW_B)            // 16896
#define OFF_B    A_PLANE
#define STAGE_B  (A_PLANE + B_PLANE)       // 27136
#define NSTAGE   4
#define HDR_OFF  (NSTAGE * STAGE_B)        // 108544
#define SMEM_TOTAL (HDR_OFF + 1024)        // 109568

// ---------------- scratch (device globals; zero-initialized) ----------------
__device__ int    g_counts[N_EXP];
__device__ int    g_token_list[N_EXP * CAP];
__device__ float  g_gate_slot[N_EXP * CAP];
__device__ __half g_xh[(size_t)T_TOK * D_MODEL];
__device__ __half g_w1[(size_t)N_EXP * D_MODEL * D_FF];
__device__ __half g_w2[(size_t)N_EXP * D_FF * D_MODEL];
__device__ __half g_hh[(size_t)N_EXP * CAP * D_FF];   // rows >= count stay 0

// ---------------- PTX helpers ------------------------------------------------
__device__ __forceinline__ uint32_t smem_u32(const void* p) {
    uint32_t a;
    asm("{ .reg .u64 t; cvta.to.shared.u64 t, %1; cvt.u32.u64 %0, t; }" : "=r"(a) : "l"(p));
    return a;
}
__device__ __forceinline__ void cp16(uint32_t dst, const void* src, int szr) {
    asm volatile("cp.async.cg.shared.global [%0], [%1], 16, %2;"
                 :: "r"(dst), "l"(src), "r"(szr) : "memory");
}
__device__ __forceinline__ void cp_commit() {
    asm volatile("cp.async.commit_group;" ::: "memory");
}
template <int N>
__device__ __forceinline__ void cp_wait() {
    asm volatile("cp.async.wait_group %0;" :: "n"(N) : "memory");
}
__device__ __forceinline__ void ldsm4(uint32_t* r, uint32_t addr) {
    asm volatile("ldmatrix.sync.aligned.m8n8.x4.shared.b16 {%0,%1,%2,%3}, [%4];"
                 : "=r"(r[0]), "=r"(r[1]), "=r"(r[2]), "=r"(r[3]) : "r"(addr));
}
__device__ __forceinline__ void ldsm4t(uint32_t* r, uint32_t addr) {
    asm volatile("ldmatrix.sync.aligned.m8n8.x4.trans.shared.b16 {%0,%1,%2,%3}, [%4];"
                 : "=r"(r[0]), "=r"(r[1]), "=r"(r[2]), "=r"(r[3]) : "r"(addr));
}
__device__ __forceinline__ void mma16816(float* c, const uint32_t* a, const uint32_t* b) {
    asm volatile(
        "mma.sync.aligned.m16n8k16.row.col.f32.f16.f16.f32 "
        "{%0,%1,%2,%3}, {%4,%5,%6,%7}, {%8,%9}, {%0,%1,%2,%3};"
        : "+f"(c[0]), "+f"(c[1]), "+f"(c[2]), "+f"(c[3])
        : "r"(a[0]), "r"(a[1]), "r"(a[2]), "r"(a[3]), "r"(b[0]), "r"(b[1]));
}

// ---------------- small kernels -----------------------------------------------
__global__ void zero_counts_kernel() {
    if (threadIdx.x < N_EXP) g_counts[threadIdx.x] = 0;
}
__global__ void zero_out_kernel(float* __restrict__ out) {
    size_t i = (size_t)blockIdx.x * blockDim.x + threadIdx.x;
    ((float4*)out)[i] = make_float4(0.f, 0.f, 0.f, 0.f);
}
// fp32 -> fp16 single plane (4 elems per thread)
__global__ void cvt_h_kernel(const float* __restrict__ src, __half* __restrict__ dst, int n4) {
    int i = blockIdx.x * blockDim.x + threadIdx.x;
    if (i >= n4) return;
    float4 v = ((const float4*)src)[i];
    ((__half2*)dst)[2 * i]     = __floats2half2_rn(v.x, v.y);
    ((__half2*)dst)[2 * i + 1] = __floats2half2_rn(v.z, v.w);
}

// ---------------- router -------------------------------------------------------
__global__ void router_kernel(const float* __restrict__ x,
                              const float* __restrict__ Wr,
                              const float* __restrict__ br) {
    int t = blockIdx.x * 8 + threadIdx.y;
    if (t >= T_TOK) return;
    int lane = threadIdx.x;

    float acc[N_EXP];
#pragma unroll
    for (int e = 0; e < N_EXP; e++) acc[e] = 0.f;
    const float* xr = x + (size_t)t * D_MODEL;
    for (int d = lane; d < D_MODEL; d += 32) {
        float xv = xr[d];
        const float* w = Wr + (size_t)d * N_EXP;
#pragma unroll
        for (int e = 0; e < N_EXP; e++) acc[e] += xv * w[e];
    }
#pragma unroll
    for (int off = 16; off > 0; off >>= 1)
#pragma unroll
        for (int e = 0; e < N_EXP; e++)
            acc[e] += __shfl_down_sync(0xffffffffu, acc[e], off);
    if (lane != 0) return;

    float p[N_EXP], mx = -1e30f, den = 0.f;
#pragma unroll
    for (int e = 0; e < N_EXP; e++) { p[e] = acc[e] + br[e]; mx = fmaxf(mx, p[e]); }
#pragma unroll
    for (int e = 0; e < N_EXP; e++) { p[e] = expf(p[e] - mx); den += p[e]; }
#pragma unroll
    for (int e = 0; e < N_EXP; e++) p[e] /= den;

    int e0 = 0;
#pragma unroll
    for (int e = 1; e < N_EXP; e++) if (p[e] > p[e0]) e0 = e;
    int e1 = (e0 == 0) ? 1 : 0;
#pragma unroll
    for (int e = 0; e < N_EXP; e++) { if (e == e0) continue; if (p[e] > p[e1]) e1 = e; }
    float s = p[e0] + p[e1];

    int i0 = atomicAdd(&g_counts[e0], 1);
    int i1 = atomicAdd(&g_counts[e1], 1);
    g_token_list[e0 * CAP + i0] = t;
    g_token_list[e1 * CAP + i1] = t;
    g_gate_slot[e0 * CAP + i0] = p[e0] / s;
    g_gate_slot[e1 * CAP + i1] = p[e1] / s;
}

// ---------------- GEMM compute step (BK=32, single fp16 term) -----------------
// warp tile 32x64: wm in 0..3 (M), wn in 0..3 (N of 256)
__device__ __forceinline__ void compute_stage(uint32_t sb, uint32_t soff,
                                              int wm, int wn, int lane,
                                              float acc[2][8][4]) {
    const uint32_t lrow = lane & 15;
    const uint32_t lhi  = (lane >> 4) << 3;
#pragma unroll
    for (int ks = 0; ks < 2; ks++) {
        uint32_t a[2][4];
#pragma unroll
        for (int mt = 0; mt < 2; mt++) {
            uint32_t addr = sb + soff
                + (uint32_t)(wm * 32 + mt * 16 + lrow) * A_ROW_B
                + (ks * 16 + lhi) * 2;
            ldsm4(a[mt], addr);
        }
        uint32_t b[8][2];
#pragma unroll
        for (int nt2 = 0; nt2 < 4; nt2++) {
            uint32_t addr = sb + soff + OFF_B
                + (uint32_t)(ks * 16 + lrow) * B_ROW_B
                + (uint32_t)(wn * 64 + nt2 * 16 + lhi) * 2;
            uint32_t t[4];
            ldsm4t(t, addr);
            b[nt2 * 2][0] = t[0];     b[nt2 * 2][1] = t[1];
            b[nt2 * 2 + 1][0] = t[2]; b[nt2 * 2 + 1][1] = t[3];
        }
#pragma unroll
        for (int mt = 0; mt < 2; mt++)
#pragma unroll
            for (int nt = 0; nt < 8; nt++)
                mma16816(acc[mt][nt], a[mt], b[nt]);
    }
}

// ---------------- GEMM1: h = relu(x[gather] @ W1[e] + b1[e]) -------------------
__global__ __launch_bounds__(512)
void gemm1_mma(const float* __restrict__ b1) {
    extern __shared__ char smem[];
    const int e = blockIdx.z;
    const int count = g_counts[e];
    const int m0 = blockIdx.y * 128;
    if (m0 >= count) return;
    const int n0 = blockIdx.x * 256;

    const int tid = threadIdx.x;
    const int lane = tid & 31, wid = tid >> 5;
    const int wm = wid & 3, wn = wid >> 2;
    const uint32_t sb = smem_u32(smem);

    int* stok = (int*)(smem + HDR_OFF);
    int* ssz  = (int*)(smem + HDR_OFF + 512);
    if (tid < 128) {
        int r = m0 + tid;
        bool v = r < count;
        stok[tid] = v ? g_token_list[e * CAP + r] : 0;
        ssz[tid]  = v ? 16 : 0;
    }
    __syncthreads();

    const __half* Bg = g_w1 + (size_t)e * D_MODEL * D_FF;

    auto issue_loads = [&](int stage, int k0) {
        {   // A: 512 cp16
            int row = tid >> 2, c4 = tid & 3;
            uint32_t dst = sb + stage * STAGE_B + (uint32_t)row * A_ROW_B + c4 * 16;
            const __half* src = g_xh + (size_t)stok[row] * D_MODEL + k0 + c4 * 8;
            cp16(dst, src, ssz[row]);
        }
#pragma unroll
        for (int h = 0; h < 2; h++) {   // B: 1024 cp16
            int idx = tid + h * 512;
            int row = idx >> 5, c16 = idx & 31;
            uint32_t dst = sb + stage * STAGE_B + OFF_B
                         + (uint32_t)row * B_ROW_B + c16 * 16;
            cp16(dst, Bg + (size_t)(k0 + row) * D_FF + n0 + c16 * 8, 16);
        }
        cp_commit();
    };

    float acc[2][8][4];
#pragma unroll
    for (int mt = 0; mt < 2; mt++)
#pragma unroll
        for (int nt = 0; nt < 8; nt++)
#pragma unroll
            for (int q = 0; q < 4; q++) acc[mt][nt][q] = 0.f;

    const int NCH = D_MODEL / 32;  // 32
    issue_loads(0, 0);
    issue_loads(1, 32);
    issue_loads(2, 64);

#pragma unroll 1
    for (int i = 0; i < NCH; i++) {
        cp_wait<2>();
        __syncthreads();
        if (i + 3 < NCH) issue_loads((i + 3) & 3, (i + 3) * 32);
        else cp_commit();
        compute_stage(sb, (i & 3) * STAGE_B, wm, wn, lane, acc);
    }

    // epilogue: bias + relu -> fp16 plane
    const int lrow = lane >> 2, lcol = (lane & 3) * 2;
    const float* b1e = b1 + (size_t)e * D_FF + n0 + wn * 64;
    float2 bias[8];
#pragma unroll
    for (int nt = 0; nt < 8; nt++) bias[nt] = *(const float2*)(b1e + nt * 8 + lcol);

#pragma unroll
    for (int mt = 0; mt < 2; mt++)
#pragma unroll
        for (int half = 0; half < 2; half++) {
            int r = m0 + wm * 32 + mt * 16 + lrow + half * 8;
            if (r >= count) continue;
            size_t base = ((size_t)e * CAP + r) * D_FF + n0 + wn * 64;
#pragma unroll
            for (int nt = 0; nt < 8; nt++) {
                float v0 = fmaxf(acc[mt][nt][half * 2 + 0] + bias[nt].x, 0.f);
                float v1 = fmaxf(acc[mt][nt][half * 2 + 1] + bias[nt].y, 0.f);
                *(__half2*)(g_hh + base + nt * 8 + lcol) = __floats2half2_rn(v0, v1);
            }
        }
}

// ---------------- GEMM2: out[tok] += gate * (h @ W2[e] + b2[e]) ----------------
__global__ __launch_bounds__(512)
void gemm2_mma(const float* __restrict__ b2, float* __restrict__ out) {
    extern __shared__ char smem[];
    const int e = blockIdx.z;
    const int count = g_counts[e];
    const int m0 = blockIdx.y * 128;
    if (m0 >= count) return;
    const int n0 = blockIdx.x * 256;

    const int tid = threadIdx.x;
    const int lane = tid & 31, wid = tid >> 5;
    const int wm = wid & 3, wn = wid >> 2;
    const uint32_t sb = smem_u32(smem);

    const __half* Bg = g_w2 + (size_t)e * D_FF * D_MODEL;
    const size_t arow0 = ((size_t)e * CAP + m0) * D_FF;

    auto issue_loads = [&](int stage, int k0) {
        {
            int row = tid >> 2, c4 = tid & 3;
            uint32_t dst = sb + stage * STAGE_B + (uint32_t)row * A_ROW_B + c4 * 16;
            cp16(dst, g_hh + arow0 + (size_t)row * D_FF + k0 + c4 * 8, 16);
        }
#pragma unroll
        for (int h = 0; h < 2; h++) {
            int idx = tid + h * 512;
            int row = idx >> 5, c16 = idx & 31;
            uint32_t dst = sb + stage * STAGE_B + OFF_B
                         + (uint32_t)row * B_ROW_B + c16 * 16;
            cp16(dst, Bg + (size_t)(k0 + row) * D_MODEL + n0 + c16 * 8, 16);
        }
        cp_commit();
    };

    float acc[2][8][4];
#pragma unroll
    for (int mt = 0; mt < 2; mt++)
#pragma unroll
        for (int nt = 0; nt < 8; nt++)
#pragma unroll
            for (int q = 0; q < 4; q++) acc[mt][nt][q] = 0.f;

    const int NCH = D_FF / 32;  // 128
    issue_loads(0, 0);
    issue_loads(1, 32);
    issue_loads(2, 64);

#pragma unroll 1
    for (int i = 0; i < NCH; i++) {
        cp_wait<2>();
        __syncthreads();
        if (i + 3 < NCH) issue_loads((i + 3) & 3, (i + 3) * 32);
        else cp_commit();
        compute_stage(sb, (i & 3) * STAGE_B, wm, wn, lane, acc);
    }

    // epilogue: bias + gate, 2-way deterministic atomic combine
    const int lrow = lane >> 2, lcol = (lane & 3) * 2;
    const float* b2e = b2 + (size_t)e * D_MODEL + n0 + wn * 64;
    float2 bias[8];
#pragma unroll
    for (int nt = 0; nt < 8; nt++) bias[nt] = *(const float2*)(b2e + nt * 8 + lcol);

#pragma unroll
    for (int mt = 0; mt < 2; mt++)
#pragma unroll
        for (int half = 0; half < 2; half++) {
            int r = m0 + wm * 32 + mt * 16 + lrow + half * 8;
            if (r >= count) continue;
            int tok = g_token_list[e * CAP + r];
            float gate = g_gate_slot[e * CAP + r];
            float* op = out + (size_t)tok * D_MODEL + n0 + wn * 64;
#pragma unroll
            for (int nt = 0; nt < 8; nt++) {
                atomicAdd(op + nt * 8 + lcol + 0, (acc[mt][nt][half * 2 + 0] + bias[nt].x) * gate);
                atomicAdd(op + nt * 8 + lcol + 1, (acc[mt][nt][half * 2 + 1] + bias[nt].y) * gate);
            }
        }
}

// ---------------- launch --------------------------------------------------------
extern "C" void kernel_launch(void* const* d_in, const int* in_sizes, int n_in,
                              void* d_out, int out_size) {
    const float* x  = (const float*)d_in[0];
    const float* Wr = (const float*)d_in[1];
    const float* br = (const float*)d_in[2];
    const float* W1 = (const float*)d_in[3];
    const float* b1 = (const float*)d_in[4];
    const float* W2 = (const float*)d_in[5];
    const float* b2 = (const float*)d_in[6];
    float* out = (float*)d_out;

    cudaFuncSetAttribute(gemm1_mma, cudaFuncAttributeMaxDynamicSharedMemorySize, SMEM_TOTAL);
    cudaFuncSetAttribute(gemm2_mma, cudaFuncAttributeMaxDynamicSharedMemorySize, SMEM_TOTAL);

    zero_counts_kernel<<<1, 32>>>();
    zero_out_kernel<<<(T_TOK * D_MODEL / 4) / 256, 256>>>(out);

    dim3 rblk(32, 8);
    router_kernel<<<T_TOK / 8, rblk>>>(x, Wr, br);

    {   // fp16 conversions
        __half* w1d; __half* w2d; __half* xd;
        cudaGetSymbolAddress((void**)&w1d, g_w1);
        cudaGetSymbolAddress((void**)&w2d, g_w2);
        cudaGetSymbolAddress((void**)&xd,  g_xh);
        int n4w = (N_EXP * D_MODEL * D_FF) / 4;
        cvt_h_kernel<<<(n4w + 255) / 256, 256>>>(W1, w1d, n4w);
        cvt_h_kernel<<<(n4w + 255) / 256, 256>>>(W2, w2d, n4w);
        int n4x = (T_TOK * D_MODEL) / 4;
        cvt_h_kernel<<<(n4x + 255) / 256, 256>>>(x, xd, n4x);
    }

    dim3 g1(D_FF / 256, CAP / 128, N_EXP);
    gemm1_mma<<<g1, 512, SMEM_TOTAL>>>(b1);

    dim3 g2(D_MODEL / 256, CAP / 128, N_EXP);
    gemm2_mma<<<g2, 512, SMEM_TOTAL>>>(b2, out);
}

// round 6
// speedup vs baseline: 5.7378x; 1.1508x over previous
#include <cuda_runtime.h>
#include <cuda_fp16.h>
#include <cstdint>
#include <math.h>

#define D_MODEL 1024
#define D_FF    4096
#define N_EXP   8
#define T_TOK   4096
#define CAP     4096

// SMEM stage geometry (bytes) — tile 128x128, BK=32
#define A_ROW_B  80                        // 32 fp16 (64B) + 16B pad
#define A_PLANE  (128 * A_ROW_B)           // 10240
#define B_ROW_B  272                       // 128 fp16 (256B) + 16B pad
#define B_PLANE  (32 * B_ROW_B)            // 8704
#define OFF_B    A_PLANE
#define STAGE_B  (A_PLANE + B_PLANE)       // 18944
#define NSTAGE   4
#define HDR_OFF  (NSTAGE * STAGE_B)        // 75776
#define SMEM_TOTAL (HDR_OFF + 1024)        // 76800  (2 CTAs/SM: 153.6 KB)

// ---------------- scratch (device globals; zero-initialized) ----------------
__device__ int    g_counts[N_EXP];
__device__ int    g_token_list[N_EXP * CAP];
__device__ float  g_gate_slot[N_EXP * CAP];
__device__ __half g_xh[(size_t)T_TOK * D_MODEL];
__device__ __half g_w1[(size_t)N_EXP * D_MODEL * D_FF];
__device__ __half g_w2[(size_t)N_EXP * D_FF * D_MODEL];
__device__ __half g_hh[(size_t)N_EXP * CAP * D_FF];   // rows >= count stay 0

// ---------------- PTX helpers ------------------------------------------------
__device__ __forceinline__ uint32_t smem_u32(const void* p) {
    uint32_t a;
    asm("{ .reg .u64 t; cvta.to.shared.u64 t, %1; cvt.u32.u64 %0, t; }" : "=r"(a) : "l"(p));
    return a;
}
__device__ __forceinline__ void cp16(uint32_t dst, const void* src, int szr) {
    asm volatile("cp.async.cg.shared.global [%0], [%1], 16, %2;"
                 :: "r"(dst), "l"(src), "r"(szr) : "memory");
}
__device__ __forceinline__ void cp_commit() {
    asm volatile("cp.async.commit_group;" ::: "memory");
}
template <int N>
__device__ __forceinline__ void cp_wait() {
    asm volatile("cp.async.wait_group %0;" :: "n"(N) : "memory");
}
__device__ __forceinline__ void ldsm4(uint32_t* r, uint32_t addr) {
    asm volatile("ldmatrix.sync.aligned.m8n8.x4.shared.b16 {%0,%1,%2,%3}, [%4];"
                 : "=r"(r[0]), "=r"(r[1]), "=r"(r[2]), "=r"(r[3]) : "r"(addr));
}
__device__ __forceinline__ void ldsm4t(uint32_t* r, uint32_t addr) {
    asm volatile("ldmatrix.sync.aligned.m8n8.x4.trans.shared.b16 {%0,%1,%2,%3}, [%4];"
                 : "=r"(r[0]), "=r"(r[1]), "=r"(r[2]), "=r"(r[3]) : "r"(addr));
}
__device__ __forceinline__ void mma16816(float* c, const uint32_t* a, const uint32_t* b) {
    asm volatile(
        "mma.sync.aligned.m16n8k16.row.col.f32.f16.f16.f32 "
        "{%0,%1,%2,%3}, {%4,%5,%6,%7}, {%8,%9}, {%0,%1,%2,%3};"
        : "+f"(c[0]), "+f"(c[1]), "+f"(c[2]), "+f"(c[3])
        : "r"(a[0]), "r"(a[1]), "r"(a[2]), "r"(a[3]), "r"(b[0]), "r"(b[1]));
}

// ---------------- small kernels -----------------------------------------------
__global__ void zero_counts_kernel() {
    if (threadIdx.x < N_EXP) g_counts[threadIdx.x] = 0;
}
__global__ void zero_out_kernel(float* __restrict__ out) {
    size_t i = (size_t)blockIdx.x * blockDim.x + threadIdx.x;
    ((float4*)out)[i] = make_float4(0.f, 0.f, 0.f, 0.f);
}
__global__ void cvt_h_kernel(const float* __restrict__ src, __half* __restrict__ dst, int n4) {
    int i = blockIdx.x * blockDim.x + threadIdx.x;
    if (i >= n4) return;
    float4 v = ((const float4*)src)[i];
    ((__half2*)dst)[2 * i]     = __floats2half2_rn(v.x, v.y);
    ((__half2*)dst)[2 * i + 1] = __floats2half2_rn(v.z, v.w);
}

// ---------------- router -------------------------------------------------------
__global__ void router_kernel(const float* __restrict__ x,
                              const float* __restrict__ Wr,
                              const float* __restrict__ br) {
    int t = blockIdx.x * 8 + threadIdx.y;
    if (t >= T_TOK) return;
    int lane = threadIdx.x;

    float acc[N_EXP];
#pragma unroll
    for (int e = 0; e < N_EXP; e++) acc[e] = 0.f;
    const float* xr = x + (size_t)t * D_MODEL;
    for (int d = lane; d < D_MODEL; d += 32) {
        float xv = xr[d];
        const float* w = Wr + (size_t)d * N_EXP;
#pragma unroll
        for (int e = 0; e < N_EXP; e++) acc[e] += xv * w[e];
    }
#pragma unroll
    for (int off = 16; off > 0; off >>= 1)
#pragma unroll
        for (int e = 0; e < N_EXP; e++)
            acc[e] += __shfl_down_sync(0xffffffffu, acc[e], off);
    if (lane != 0) return;

    float p[N_EXP], mx = -1e30f, den = 0.f;
#pragma unroll
    for (int e = 0; e < N_EXP; e++) { p[e] = acc[e] + br[e]; mx = fmaxf(mx, p[e]); }
#pragma unroll
    for (int e = 0; e < N_EXP; e++) { p[e] = expf(p[e] - mx); den += p[e]; }
#pragma unroll
    for (int e = 0; e < N_EXP; e++) p[e] /= den;

    int e0 = 0;
#pragma unroll
    for (int e = 1; e < N_EXP; e++) if (p[e] > p[e0]) e0 = e;
    int e1 = (e0 == 0) ? 1 : 0;
#pragma unroll
    for (int e = 0; e < N_EXP; e++) { if (e == e0) continue; if (p[e] > p[e1]) e1 = e; }
    float s = p[e0] + p[e1];

    int i0 = atomicAdd(&g_counts[e0], 1);
    int i1 = atomicAdd(&g_counts[e1], 1);
    g_token_list[e0 * CAP + i0] = t;
    g_token_list[e1 * CAP + i1] = t;
    g_gate_slot[e0 * CAP + i0] = p[e0] / s;
    g_gate_slot[e1 * CAP + i1] = p[e1] / s;
}

// ---------------- GEMM compute step (BK=32, warp tile 32x64 of 128-N tile) ----
__device__ __forceinline__ void compute_stage(uint32_t sb, uint32_t soff,
                                              int wm, int wn, int lane,
                                              float acc[2][8][4]) {
    const uint32_t lrow = lane & 15;
    const uint32_t lhi  = (lane >> 4) << 3;
#pragma unroll
    for (int ks = 0; ks < 2; ks++) {
        uint32_t a[2][4];
#pragma unroll
        for (int mt = 0; mt < 2; mt++) {
            uint32_t addr = sb + soff
                + (uint32_t)(wm * 32 + mt * 16 + lrow) * A_ROW_B
                + (ks * 16 + lhi) * 2;
            ldsm4(a[mt], addr);
        }
        uint32_t b[8][2];
#pragma unroll
        for (int nt2 = 0; nt2 < 4; nt2++) {
            uint32_t addr = sb + soff + OFF_B
                + (uint32_t)(ks * 16 + lrow) * B_ROW_B
                + (uint32_t)(wn * 64 + nt2 * 16 + lhi) * 2;
            uint32_t t[4];
            ldsm4t(t, addr);
            b[nt2 * 2][0] = t[0];     b[nt2 * 2][1] = t[1];
            b[nt2 * 2 + 1][0] = t[2]; b[nt2 * 2 + 1][1] = t[3];
        }
#pragma unroll
        for (int mt = 0; mt < 2; mt++)
#pragma unroll
            for (int nt = 0; nt < 8; nt++)
                mma16816(acc[mt][nt], a[mt], b[nt]);
    }
}

// ---------------- GEMM1: h = relu(x[gather] @ W1[e] + b1[e]) -------------------
__global__ __launch_bounds__(256, 2)
void gemm1_mma(const float* __restrict__ b1) {
    extern __shared__ char smem[];
    const int e = blockIdx.z;
    const int count = g_counts[e];
    const int m0 = blockIdx.y * 128;
    if (m0 >= count) return;
    const int n0 = blockIdx.x * 128;

    const int tid = threadIdx.x;
    const int lane = tid & 31, wid = tid >> 5;
    const int wm = wid & 3, wn = wid >> 2;
    const uint32_t sb = smem_u32(smem);

    int* stok = (int*)(smem + HDR_OFF);
    int* ssz  = (int*)(smem + HDR_OFF + 512);
    if (tid < 128) {
        int r = m0 + tid;
        bool v = r < count;
        stok[tid] = v ? g_token_list[e * CAP + r] : 0;
        ssz[tid]  = v ? 16 : 0;
    }
    __syncthreads();

    const __half* Bg = g_w1 + (size_t)e * D_MODEL * D_FF;

    auto issue_loads = [&](int stage, int k0) {
#pragma unroll
        for (int h = 0; h < 2; h++) {   // A: 512 cp16
            int idx = tid + h * 256;
            int row = idx >> 2, c4 = idx & 3;
            uint32_t dst = sb + stage * STAGE_B + (uint32_t)row * A_ROW_B + c4 * 16;
            cp16(dst, g_xh + (size_t)stok[row] * D_MODEL + k0 + c4 * 8, ssz[row]);
        }
#pragma unroll
        for (int h = 0; h < 2; h++) {   // B: 512 cp16
            int idx = tid + h * 256;
            int row = idx >> 4, c16 = idx & 15;
            uint32_t dst = sb + stage * STAGE_B + OFF_B
                         + (uint32_t)row * B_ROW_B + c16 * 16;
            cp16(dst, Bg + (size_t)(k0 + row) * D_FF + n0 + c16 * 8, 16);
        }
        cp_commit();
    };

    float acc[2][8][4];
#pragma unroll
    for (int mt = 0; mt < 2; mt++)
#pragma unroll
        for (int nt = 0; nt < 8; nt++)
#pragma unroll
            for (int q = 0; q < 4; q++) acc[mt][nt][q] = 0.f;

    const int NCH = D_MODEL / 32;  // 32
    issue_loads(0, 0);
    issue_loads(1, 32);
    issue_loads(2, 64);

#pragma unroll 1
    for (int i = 0; i < NCH; i++) {
        cp_wait<2>();
        __syncthreads();
        if (i + 3 < NCH) issue_loads((i + 3) & 3, (i + 3) * 32);
        else cp_commit();
        compute_stage(sb, (i & 3) * STAGE_B, wm, wn, lane, acc);
    }

    // epilogue: bias + relu -> fp16 plane
    const int lrow = lane >> 2, lcol = (lane & 3) * 2;
    const float* b1e = b1 + (size_t)e * D_FF + n0 + wn * 64;
    float2 bias[8];
#pragma unroll
    for (int nt = 0; nt < 8; nt++) bias[nt] = *(const float2*)(b1e + nt * 8 + lcol);

#pragma unroll
    for (int mt = 0; mt < 2; mt++)
#pragma unroll
        for (int half = 0; half < 2; half++) {
            int r = m0 + wm * 32 + mt * 16 + lrow + half * 8;
            if (r >= count) continue;
            size_t base = ((size_t)e * CAP + r) * D_FF + n0 + wn * 64;
#pragma unroll
            for (int nt = 0; nt < 8; nt++) {
                float v0 = fmaxf(acc[mt][nt][half * 2 + 0] + bias[nt].x, 0.f);
                float v1 = fmaxf(acc[mt][nt][half * 2 + 1] + bias[nt].y, 0.f);
                *(__half2*)(g_hh + base + nt * 8 + lcol) = __floats2half2_rn(v0, v1);
            }
        }
}

// ---------------- GEMM2 (split-K=2): out[tok] += gate*(h @ W2[e] + b2[e]) ------
__global__ __launch_bounds__(256, 2)
void gemm2_mma(const float* __restrict__ b2, float* __restrict__ out) {
    extern __shared__ char smem[];
    const int e = blockIdx.z >> 1;
    const int split = blockIdx.z & 1;
    const int count = g_counts[e];
    const int m0 = blockIdx.y * 128;
    if (m0 >= count) return;
    const int n0 = blockIdx.x * 128;
    const int kbase = split * (D_FF / 2);

    const int tid = threadIdx.x;
    const int lane = tid & 31, wid = tid >> 5;
    const int wm = wid & 3, wn = wid >> 2;
    const uint32_t sb = smem_u32(smem);

    const __half* Bg = g_w2 + (size_t)e * D_FF * D_MODEL;
    const size_t arow0 = ((size_t)e * CAP + m0) * D_FF + kbase;

    auto issue_loads = [&](int stage, int k0) {
#pragma unroll
        for (int h = 0; h < 2; h++) {
            int idx = tid + h * 256;
            int row = idx >> 2, c4 = idx & 3;
            uint32_t dst = sb + stage * STAGE_B + (uint32_t)row * A_ROW_B + c4 * 16;
            cp16(dst, g_hh + arow0 + (size_t)row * D_FF + k0 + c4 * 8, 16);
        }
#pragma unroll
        for (int h = 0; h < 2; h++) {
            int idx = tid + h * 256;
            int row = idx >> 4, c16 = idx & 15;
            uint32_t dst = sb + stage * STAGE_B + OFF_B
                         + (uint32_t)row * B_ROW_B + c16 * 16;
            cp16(dst, Bg + (size_t)(kbase + k0 + row) * D_MODEL + n0 + c16 * 8, 16);
        }
        cp_commit();
    };

    float acc[2][8][4];
#pragma unroll
    for (int mt = 0; mt < 2; mt++)
#pragma unroll
        for (int nt = 0; nt < 8; nt++)
#pragma unroll
            for (int q = 0; q < 4; q++) acc[mt][nt][q] = 0.f;

    const int NCH = (D_FF / 2) / 32;  // 64
    issue_loads(0, 0);
    issue_loads(1, 32);
    issue_loads(2, 64);

#pragma unroll 1
    for (int i = 0; i < NCH; i++) {
        cp_wait<2>();
        __syncthreads();
        if (i + 3 < NCH) issue_loads((i + 3) & 3, (i + 3) * 32);
        else cp_commit();
        compute_stage(sb, (i & 3) * STAGE_B, wm, wn, lane, acc);
    }

    // epilogue: (bias only from split 0) + gate, deterministic-enough atomics
    const int lrow = lane >> 2, lcol = (lane & 3) * 2;
    const float* b2e = b2 + (size_t)e * D_MODEL + n0 + wn * 64;
    float2 bias[8];
#pragma unroll
    for (int nt = 0; nt < 8; nt++) {
        if (split == 0) bias[nt] = *(const float2*)(b2e + nt * 8 + lcol);
        else            bias[nt] = make_float2(0.f, 0.f);
    }

#pragma unroll
    for (int mt = 0; mt < 2; mt++)
#pragma unroll
        for (int half = 0; half < 2; half++) {
            int r = m0 + wm * 32 + mt * 16 + lrow + half * 8;
            if (r >= count) continue;
            int tok = g_token_list[e * CAP + r];
            float gate = g_gate_slot[e * CAP + r];
            float* op = out + (size_t)tok * D_MODEL + n0 + wn * 64;
#pragma unroll
            for (int nt = 0; nt < 8; nt++) {
                atomicAdd(op + nt * 8 + lcol + 0, (acc[mt][nt][half * 2 + 0] + bias[nt].x) * gate);
                atomicAdd(op + nt * 8 + lcol + 1, (acc[mt][nt][half * 2 + 1] + bias[nt].y) * gate);
            }
        }
}

// ---------------- launch --------------------------------------------------------
extern "C" void kernel_launch(void* const* d_in, const int* in_sizes, int n_in,
                              void* d_out, int out_size) {
    const float* x  = (const float*)d_in[0];
    const float* Wr = (const float*)d_in[1];
    const float* br = (const float*)d_in[2];
    const float* W1 = (const float*)d_in[3];
    const float* b1 = (const float*)d_in[4];
    const float* W2 = (const float*)d_in[5];
    const float* b2 = (const float*)d_in[6];
    float* out = (float*)d_out;

    cudaFuncSetAttribute(gemm1_mma, cudaFuncAttributeMaxDynamicSharedMemorySize, SMEM_TOTAL);
    cudaFuncSetAttribute(gemm2_mma, cudaFuncAttributeMaxDynamicSharedMemorySize, SMEM_TOTAL);

    zero_counts_kernel<<<1, 32>>>();
    zero_out_kernel<<<(T_TOK * D_MODEL / 4) / 256, 256>>>(out);

    dim3 rblk(32, 8);
    router_kernel<<<T_TOK / 8, rblk>>>(x, Wr, br);

    {   // fp16 conversions
        __half* w1d; __half* w2d; __half* xd;
        cudaGetSymbolAddress((void**)&w1d, g_w1);
        cudaGetSymbolAddress((void**)&w2d, g_w2);
        cudaGetSymbolAddress((void**)&xd,  g_xh);
        int n4w = (N_EXP * D_MODEL * D_FF) / 4;
        cvt_h_kernel<<<(n4w + 255) / 256, 256>>>(W1, w1d, n4w);
        cvt_h_kernel<<<(n4w + 255) / 256, 256>>>(W2, w2d, n4w);
        int n4x = (T_TOK * D_MODEL) / 4;
        cvt_h_kernel<<<(n4x + 255) / 256, 256>>>(x, xd, n4x);
    }

    dim3 g1(D_FF / 128, CAP / 128, N_EXP);
    gemm1_mma<<<g1, 256, SMEM_TOTAL>>>(b1);

    dim3 g2(D_MODEL / 128, CAP / 128, N_EXP * 2);
    gemm2_mma<<<g2, 256, SMEM_TOTAL>>>(b2, out);
}

// round 8
// speedup vs baseline: 6.0026x; 1.0462x over previous
#include <cuda_runtime.h>
#include <cuda_fp16.h>
#include <cstdint>
#include <math.h>

#define D_MODEL 1024
#define D_FF    4096
#define N_EXP   8
#define T_TOK   4096
#define CAP     4096

// SMEM stage geometry (bytes) — tile 128x128, BK=32, 4 stages (round-6 proven)
#define A_ROW_B  80                        // 32 fp16 (64B) + 16B pad
#define A_PLANE  (128 * A_ROW_B)           // 10240
#define B_ROW_B  272                       // 128 fp16 (256B) + 16B pad
#define B_PLANE  (32 * B_ROW_B)            // 8704
#define OFF_B    A_PLANE
#define STAGE_B  (A_PLANE + B_PLANE)       // 18944
#define NSTAGE   4
#define HDR_OFF  (NSTAGE * STAGE_B)        // 75776
#define SMEM_TOTAL (HDR_OFF + 1024)        // 76800  (2 CTAs/SM: 153.6 KB)

#define ROUTER_BLOCKS (T_TOK / 8)          // 512
#define CONV_BLOCKS   4096

// ---------------- scratch (device globals; zero-initialized) ----------------
__device__ int    g_counts[N_EXP];
__device__ int    g_token_list[N_EXP * CAP];
__device__ float  g_gate_slot[N_EXP * CAP];
__device__ __half g_xh[(size_t)T_TOK * D_MODEL];
__device__ __half g_w1[(size_t)N_EXP * D_MODEL * D_FF];
__device__ __half g_w2[(size_t)N_EXP * D_FF * D_MODEL];
__device__ __half g_hh[(size_t)N_EXP * CAP * D_FF];   // rows >= count stay 0

// ---------------- PTX helpers ------------------------------------------------
__device__ __forceinline__ uint32_t smem_u32(const void* p) {
    uint32_t a;
    asm("{ .reg .u64 t; cvta.to.shared.u64 t, %1; cvt.u32.u64 %0, t; }" : "=r"(a) : "l"(p));
    return a;
}
__device__ __forceinline__ void cp16(uint32_t dst, const void* src, int szr) {
    asm volatile("cp.async.cg.shared.global [%0], [%1], 16, %2;"
                 :: "r"(dst), "l"(src), "r"(szr) : "memory");
}
__device__ __forceinline__ void cp_commit() {
    asm volatile("cp.async.commit_group;" ::: "memory");
}
template <int N>
__device__ __forceinline__ void cp_wait() {
    asm volatile("cp.async.wait_group %0;" :: "n"(N) : "memory");
}
__device__ __forceinline__ void ldsm4(uint32_t* r, uint32_t addr) {
    asm volatile("ldmatrix.sync.aligned.m8n8.x4.shared.b16 {%0,%1,%2,%3}, [%4];"
                 : "=r"(r[0]), "=r"(r[1]), "=r"(r[2]), "=r"(r[3]) : "r"(addr));
}
__device__ __forceinline__ void ldsm4t(uint32_t* r, uint32_t addr) {
    asm volatile("ldmatrix.sync.aligned.m8n8.x4.trans.shared.b16 {%0,%1,%2,%3}, [%4];"
                 : "=r"(r[0]), "=r"(r[1]), "=r"(r[2]), "=r"(r[3]) : "r"(addr));
}
__device__ __forceinline__ void mma16816(float* c, const uint32_t* a, const uint32_t* b) {
    asm volatile(
        "mma.sync.aligned.m16n8k16.row.col.f32.f16.f16.f32 "
        "{%0,%1,%2,%3}, {%4,%5,%6,%7}, {%8,%9}, {%0,%1,%2,%3};"
        : "+f"(c[0]), "+f"(c[1]), "+f"(c[2]), "+f"(c[3])
        : "r"(a[0]), "r"(a[1]), "r"(a[2]), "r"(a[3]), "r"(b[0]), "r"(b[1]));
}

// ---------------- small kernels -----------------------------------------------
__global__ void zero_counts_kernel() {
    if (threadIdx.x < N_EXP) g_counts[threadIdx.x] = 0;
}

// ---------------- fused prep: router + fp16 conversions + out zeroing ----------
__global__ __launch_bounds__(256)
void prep_kernel(const float* __restrict__ x, const float* __restrict__ Wr,
                 const float* __restrict__ br, const float* __restrict__ W1,
                 const float* __restrict__ W2, float* __restrict__ out) {
    if (blockIdx.x < ROUTER_BLOCKS) {
        // ---- router: 8 tokens per block, one warp per token ----
        const int tid = threadIdx.x;
        const int lane = tid & 31;
        const int t = blockIdx.x * 8 + (tid >> 5);

        float acc[N_EXP];
#pragma unroll
        for (int e = 0; e < N_EXP; e++) acc[e] = 0.f;
        const float* xr = x + (size_t)t * D_MODEL;
        for (int d = lane; d < D_MODEL; d += 32) {
            float xv = xr[d];
            const float* w = Wr + (size_t)d * N_EXP;
#pragma unroll
            for (int e = 0; e < N_EXP; e++) acc[e] += xv * w[e];
        }
#pragma unroll
        for (int off = 16; off > 0; off >>= 1)
#pragma unroll
            for (int e = 0; e < N_EXP; e++)
                acc[e] += __shfl_down_sync(0xffffffffu, acc[e], off);
        if (lane != 0) return;

        float p[N_EXP], mx = -1e30f, den = 0.f;
#pragma unroll
        for (int e = 0; e < N_EXP; e++) { p[e] = acc[e] + br[e]; mx = fmaxf(mx, p[e]); }
#pragma unroll
        for (int e = 0; e < N_EXP; e++) { p[e] = expf(p[e] - mx); den += p[e]; }
#pragma unroll
        for (int e = 0; e < N_EXP; e++) p[e] /= den;

        int e0 = 0;
#pragma unroll
        for (int e = 1; e < N_EXP; e++) if (p[e] > p[e0]) e0 = e;
        int e1 = (e0 == 0) ? 1 : 0;
#pragma unroll
        for (int e = 0; e < N_EXP; e++) { if (e == e0) continue; if (p[e] > p[e1]) e1 = e; }
        float s = p[e0] + p[e1];

        int i0 = atomicAdd(&g_counts[e0], 1);
        int i1 = atomicAdd(&g_counts[e1], 1);
        g_token_list[e0 * CAP + i0] = t;
        g_token_list[e1 * CAP + i1] = t;
        g_gate_slot[e0 * CAP + i0] = p[e0] / s;
        g_gate_slot[e1 * CAP + i1] = p[e1] / s;
    } else {
        // ---- conversions + out zeroing, grid-strided over float4 items ----
        const size_t n4x = (size_t)T_TOK * D_MODEL / 4;
        const size_t n4w = (size_t)N_EXP * D_MODEL * D_FF / 4;
        const size_t n4o = (size_t)T_TOK * D_MODEL / 4;
        const size_t b0 = n4x, b1 = n4x + n4w, b2 = n4x + 2 * n4w;
        const size_t total = b2 + n4o;
        const size_t stride = (size_t)CONV_BLOCKS * 256;
        size_t i = (size_t)(blockIdx.x - ROUTER_BLOCKS) * 256 + threadIdx.x;
        for (; i < total; i += stride) {
            if (i < b0) {
                float4 v = ((const float4*)x)[i];
                ((__half2*)g_xh)[2 * i]     = __floats2half2_rn(v.x, v.y);
                ((__half2*)g_xh)[2 * i + 1] = __floats2half2_rn(v.z, v.w);
            } else if (i < b1) {
                size_t j = i - b0;
                float4 v = ((const float4*)W1)[j];
                ((__half2*)g_w1)[2 * j]     = __floats2half2_rn(v.x, v.y);
                ((__half2*)g_w1)[2 * j + 1] = __floats2half2_rn(v.z, v.w);
            } else if (i < b2) {
                size_t j = i - b1;
                float4 v = ((const float4*)W2)[j];
                ((__half2*)g_w2)[2 * j]     = __floats2half2_rn(v.x, v.y);
                ((__half2*)g_w2)[2 * j + 1] = __floats2half2_rn(v.z, v.w);
            } else {
                ((float4*)out)[i - b2] = make_float4(0.f, 0.f, 0.f, 0.f);
            }
        }
    }
}

// ---------------- GEMM compute step (BK=32, warp tile 32x64 of 128-N tile) ----
__device__ __forceinline__ void compute_stage(uint32_t sb, uint32_t soff,
                                              int wm, int wn, int lane,
                                              float acc[2][8][4]) {
    const uint32_t lrow = lane & 15;
    const uint32_t lhi  = (lane >> 4) << 3;
#pragma unroll
    for (int ks = 0; ks < 2; ks++) {
        uint32_t a[2][4];
#pragma unroll
        for (int mt = 0; mt < 2; mt++) {
            uint32_t addr = sb + soff
                + (uint32_t)(wm * 32 + mt * 16 + lrow) * A_ROW_B
                + (ks * 16 + lhi) * 2;
            ldsm4(a[mt], addr);
        }
        uint32_t b[8][2];
#pragma unroll
        for (int nt2 = 0; nt2 < 4; nt2++) {
            uint32_t addr = sb + soff + OFF_B
                + (uint32_t)(ks * 16 + lrow) * B_ROW_B
                + (uint32_t)(wn * 64 + nt2 * 16 + lhi) * 2;
            uint32_t t[4];
            ldsm4t(t, addr);
            b[nt2 * 2][0] = t[0];     b[nt2 * 2][1] = t[1];
            b[nt2 * 2 + 1][0] = t[2]; b[nt2 * 2 + 1][1] = t[3];
        }
#pragma unroll
        for (int mt = 0; mt < 2; mt++)
#pragma unroll
            for (int nt = 0; nt < 8; nt++)
                mma16816(acc[mt][nt], a[mt], b[nt]);
    }
}

// ---------------- GEMM1: h = relu(x[gather] @ W1[e] + b1[e]) -------------------
__global__ __launch_bounds__(256, 2)
void gemm1_mma(const float* __restrict__ b1) {
    extern __shared__ char smem[];
    const int e = blockIdx.z;
    const int count = g_counts[e];
    const int m0 = blockIdx.y * 128;
    if (m0 >= count) return;
    const int n0 = blockIdx.x * 128;

    const int tid = threadIdx.x;
    const int lane = tid & 31, wid = tid >> 5;
    const int wm = wid & 3, wn = wid >> 2;
    const uint32_t sb = smem_u32(smem);

    int* stok = (int*)(smem + HDR_OFF);
    int* ssz  = (int*)(smem + HDR_OFF + 512);
    if (tid < 128) {
        int r = m0 + tid;
        bool v = r < count;
        stok[tid] = v ? g_token_list[e * CAP + r] : 0;
        ssz[tid]  = v ? 16 : 0;
    }
    __syncthreads();

    const __half* Bg = g_w1 + (size_t)e * D_MODEL * D_FF;

    auto issue_loads = [&](int stage, int k0) {
#pragma unroll
        for (int h = 0; h < 2; h++) {   // A: 512 cp16
            int idx = tid + h * 256;
            int row = idx >> 2, c4 = idx & 3;
            uint32_t dst = sb + stage * STAGE_B + (uint32_t)row * A_ROW_B + c4 * 16;
            cp16(dst, g_xh + (size_t)stok[row] * D_MODEL + k0 + c4 * 8, ssz[row]);
        }
#pragma unroll
        for (int h = 0; h < 2; h++) {   // B: 512 cp16
            int idx = tid + h * 256;
            int row = idx >> 4, c16 = idx & 15;
            uint32_t dst = sb + stage * STAGE_B + OFF_B
                         + (uint32_t)row * B_ROW_B + c16 * 16;
            cp16(dst, Bg + (size_t)(k0 + row) * D_FF + n0 + c16 * 8, 16);
        }
        cp_commit();
    };

    float acc[2][8][4];
#pragma unroll
    for (int mt = 0; mt < 2; mt++)
#pragma unroll
        for (int nt = 0; nt < 8; nt++)
#pragma unroll
            for (int q = 0; q < 4; q++) acc[mt][nt][q] = 0.f;

    const int NCH = D_MODEL / 32;  // 32
    issue_loads(0, 0);
    issue_loads(1, 32);
    issue_loads(2, 64);

#pragma unroll 1
    for (int i = 0; i < NCH; i++) {
        cp_wait<2>();
        __syncthreads();
        if (i + 3 < NCH) issue_loads((i + 3) & 3, (i + 3) * 32);
        else cp_commit();
        compute_stage(sb, (i & 3) * STAGE_B, wm, wn, lane, acc);
    }

    // epilogue: bias + relu -> fp16 plane
    const int lrow = lane >> 2, lcol = (lane & 3) * 2;
    const float* b1e = b1 + (size_t)e * D_FF + n0 + wn * 64;
    float2 bias[8];
#pragma unroll
    for (int nt = 0; nt < 8; nt++) bias[nt] = *(const float2*)(b1e + nt * 8 + lcol);

#pragma unroll
    for (int mt = 0; mt < 2; mt++)
#pragma unroll
        for (int half = 0; half < 2; half++) {
            int r = m0 + wm * 32 + mt * 16 + lrow + half * 8;
            if (r >= count) continue;
            size_t base = ((size_t)e * CAP + r) * D_FF + n0 + wn * 64;
#pragma unroll
            for (int nt = 0; nt < 8; nt++) {
                float v0 = fmaxf(acc[mt][nt][half * 2 + 0] + bias[nt].x, 0.f);
                float v1 = fmaxf(acc[mt][nt][half * 2 + 1] + bias[nt].y, 0.f);
                *(__half2*)(g_hh + base + nt * 8 + lcol) = __floats2half2_rn(v0, v1);
            }
        }
}

// ---------------- GEMM2 (split-K=2): out[tok] += gate*(h @ W2[e] + b2[e]) ------
__global__ __launch_bounds__(256, 2)
void gemm2_mma(const float* __restrict__ b2, float* __restrict__ out) {
    extern __shared__ char smem[];
    const int e = blockIdx.z >> 1;
    const int split = blockIdx.z & 1;
    const int count = g_counts[e];
    const int m0 = blockIdx.y * 128;
    if (m0 >= count) return;
    const int n0 = blockIdx.x * 128;
    const int kbase = split * (D_FF / 2);

    const int tid = threadIdx.x;
    const int lane = tid & 31, wid = tid >> 5;
    const int wm = wid & 3, wn = wid >> 2;
    const uint32_t sb = smem_u32(smem);

    const __half* Bg = g_w2 + (size_t)e * D_FF * D_MODEL;
    const size_t arow0 = ((size_t)e * CAP + m0) * D_FF + kbase;

    auto issue_loads = [&](int stage, int k0) {
#pragma unroll
        for (int h = 0; h < 2; h++) {
            int idx = tid + h * 256;
            int row = idx >> 2, c4 = idx & 3;
            uint32_t dst = sb + stage * STAGE_B + (uint32_t)row * A_ROW_B + c4 * 16;
            cp16(dst, g_hh + arow0 + (size_t)row * D_FF + k0 + c4 * 8, 16);
        }
#pragma unroll
        for (int h = 0; h < 2; h++) {
            int idx = tid + h * 256;
            int row = idx >> 4, c16 = idx & 15;
            uint32_t dst = sb + stage * STAGE_B + OFF_B
                         + (uint32_t)row * B_ROW_B + c16 * 16;
            cp16(dst, Bg + (size_t)(kbase + k0 + row) * D_MODEL + n0 + c16 * 8, 16);
        }
        cp_commit();
    };

    float acc[2][8][4];
#pragma unroll
    for (int mt = 0; mt < 2; mt++)
#pragma unroll
        for (int nt = 0; nt < 8; nt++)
#pragma unroll
            for (int q = 0; q < 4; q++) acc[mt][nt][q] = 0.f;

    const int NCH = (D_FF / 2) / 32;  // 64
    issue_loads(0, 0);
    issue_loads(1, 32);
    issue_loads(2, 64);

#pragma unroll 1
    for (int i = 0; i < NCH; i++) {
        cp_wait<2>();
        __syncthreads();
        if (i + 3 < NCH) issue_loads((i + 3) & 3, (i + 3) * 32);
        else cp_commit();
        compute_stage(sb, (i & 3) * STAGE_B, wm, wn, lane, acc);
    }

    // epilogue: (bias only from split 0) + gate, commutative atomic combine
    const int lrow = lane >> 2, lcol = (lane & 3) * 2;
    const float* b2e = b2 + (size_t)e * D_MODEL + n0 + wn * 64;
    float2 bias[8];
#pragma unroll
    for (int nt = 0; nt < 8; nt++) {
        if (split == 0) bias[nt] = *(const float2*)(b2e + nt * 8 + lcol);
        else            bias[nt] = make_float2(0.f, 0.f);
    }

#pragma unroll
    for (int mt = 0; mt < 2; mt++)
#pragma unroll
        for (int half = 0; half < 2; half++) {
            int r = m0 + wm * 32 + mt * 16 + lrow + half * 8;
            if (r >= count) continue;
            int tok = g_token_list[e * CAP + r];
            float gate = g_gate_slot[e * CAP + r];
            float* op = out + (size_t)tok * D_MODEL + n0 + wn * 64;
#pragma unroll
            for (int nt = 0; nt < 8; nt++) {
                atomicAdd(op + nt * 8 + lcol + 0, (acc[mt][nt][half * 2 + 0] + bias[nt].x) * gate);
                atomicAdd(op + nt * 8 + lcol + 1, (acc[mt][nt][half * 2 + 1] + bias[nt].y) * gate);
            }
        }
}

// ---------------- launch --------------------------------------------------------
extern "C" void kernel_launch(void* const* d_in, const int* in_sizes, int n_in,
                              void* d_out, int out_size) {
    const float* x  = (const float*)d_in[0];
    const float* Wr = (const float*)d_in[1];
    const float* br = (const float*)d_in[2];
    const float* W1 = (const float*)d_in[3];
    const float* b1 = (const float*)d_in[4];
    const float* W2 = (const float*)d_in[5];
    const float* b2 = (const float*)d_in[6];
    float* out = (float*)d_out;

    cudaFuncSetAttribute(gemm1_mma, cudaFuncAttributeMaxDynamicSharedMemorySize, SMEM_TOTAL);
    cudaFuncSetAttribute(gemm2_mma, cudaFuncAttributeMaxDynamicSharedMemorySize, SMEM_TOTAL);

    zero_counts_kernel<<<1, 32>>>();

    // fused prep: router + all fp16 conversions + out zeroing, one launch
    prep_kernel<<<ROUTER_BLOCKS + CONV_BLOCKS, 256>>>(x, Wr, br, W1, W2, out);

    dim3 g1(D_FF / 128, CAP / 128, N_EXP);
    gemm1_mma<<<g1, 256, SMEM_TOTAL>>>(b1);

    dim3 g2(D_MODEL / 128, CAP / 128, N_EXP * 2);
    gemm2_mma<<<g2, 256, SMEM_TOTAL>>>(b2, out);
}

// round 9
// speedup vs baseline: 6.7837x; 1.1301x over previous
#include <cuda_runtime.h>
#include <cuda_fp16.h>
#include <cstdint>
#include <math.h>

#define D_MODEL 1024
#define D_FF    4096
#define N_EXP   8
#define T_TOK   4096
#define CAP     4096

// SMEM stage geometry (bytes) — tile 128x128, BK=32, 4 stages
#define A_ROW_B  80                        // 32 fp16 (64B) + 16B pad
#define A_PLANE  (128 * A_ROW_B)           // 10240
#define B_ROW_B  272                       // 128 fp16 (256B) + 16B pad
#define B_PLANE  (32 * B_ROW_B)            // 8704
#define OFF_B    A_PLANE
#define STAGE_B  (A_PLANE + B_PLANE)       // 18944
#define NSTAGE   4
#define HDR_OFF  (NSTAGE * STAGE_B)        // 75776
#define SMEM_TOTAL (HDR_OFF + 1024)        // 76800  (2 CTAs/SM: 153.6 KB)

#define ROUTER_BLOCKS (T_TOK / 8)          // 512
#define CONV_BLOCKS   4096

// ---------------- scratch (device globals; zero-initialized) ----------------
__device__ int    g_counts[N_EXP];
__device__ int    g_token_list[N_EXP * CAP];
__device__ float  g_gate_slot[N_EXP * CAP];
__device__ __half g_xh[(size_t)T_TOK * D_MODEL];
__device__ __half g_w1[(size_t)N_EXP * D_MODEL * D_FF];
__device__ __half g_w2[(size_t)N_EXP * D_FF * D_MODEL];
__device__ __half g_hh[(size_t)N_EXP * CAP * D_FF];   // rows >= count stay 0

// ---------------- PTX helpers ------------------------------------------------
__device__ __forceinline__ uint32_t smem_u32(const void* p) {
    uint32_t a;
    asm("{ .reg .u64 t; cvta.to.shared.u64 t, %1; cvt.u32.u64 %0, t; }" : "=r"(a) : "l"(p));
    return a;
}
__device__ __forceinline__ void cp16(uint32_t dst, const void* src, int szr) {
    asm volatile("cp.async.cg.shared.global [%0], [%1], 16, %2;"
                 :: "r"(dst), "l"(src), "r"(szr) : "memory");
}
__device__ __forceinline__ void cp_commit() {
    asm volatile("cp.async.commit_group;" ::: "memory");
}
template <int N>
__device__ __forceinline__ void cp_wait() {
    asm volatile("cp.async.wait_group %0;" :: "n"(N) : "memory");
}
__device__ __forceinline__ void ldsm4(uint32_t* r, uint32_t addr) {
    asm volatile("ldmatrix.sync.aligned.m8n8.x4.shared.b16 {%0,%1,%2,%3}, [%4];"
                 : "=r"(r[0]), "=r"(r[1]), "=r"(r[2]), "=r"(r[3]) : "r"(addr));
}
__device__ __forceinline__ void ldsm4t(uint32_t* r, uint32_t addr) {
    asm volatile("ldmatrix.sync.aligned.m8n8.x4.trans.shared.b16 {%0,%1,%2,%3}, [%4];"
                 : "=r"(r[0]), "=r"(r[1]), "=r"(r[2]), "=r"(r[3]) : "r"(addr));
}
__device__ __forceinline__ void mma16816(float* c, const uint32_t* a, const uint32_t* b) {
    asm volatile(
        "mma.sync.aligned.m16n8k16.row.col.f32.f16.f16.f32 "
        "{%0,%1,%2,%3}, {%4,%5,%6,%7}, {%8,%9}, {%0,%1,%2,%3};"
        : "+f"(c[0]), "+f"(c[1]), "+f"(c[2]), "+f"(c[3])
        : "r"(a[0]), "r"(a[1]), "r"(a[2]), "r"(a[3]), "r"(b[0]), "r"(b[1]));
}

// ---------------- small kernels -----------------------------------------------
__global__ void zero_counts_kernel() {
    if (threadIdx.x < N_EXP) g_counts[threadIdx.x] = 0;
}

// ---------------- fused prep: router + fp16 conversions + out zeroing ----------
__global__ __launch_bounds__(256)
void prep_kernel(const float* __restrict__ x, const float* __restrict__ Wr,
                 const float* __restrict__ br, const float* __restrict__ W1,
                 const float* __restrict__ W2, float* __restrict__ out) {
    if (blockIdx.x < ROUTER_BLOCKS) {
        const int tid = threadIdx.x;
        const int lane = tid & 31;
        const int t = blockIdx.x * 8 + (tid >> 5);

        float acc[N_EXP];
#pragma unroll
        for (int e = 0; e < N_EXP; e++) acc[e] = 0.f;
        const float* xr = x + (size_t)t * D_MODEL;
        for (int d = lane; d < D_MODEL; d += 32) {
            float xv = xr[d];
            const float* w = Wr + (size_t)d * N_EXP;
#pragma unroll
            for (int e = 0; e < N_EXP; e++) acc[e] += xv * w[e];
        }
#pragma unroll
        for (int off = 16; off > 0; off >>= 1)
#pragma unroll
            for (int e = 0; e < N_EXP; e++)
                acc[e] += __shfl_down_sync(0xffffffffu, acc[e], off);
        if (lane != 0) return;

        float p[N_EXP], mx = -1e30f, den = 0.f;
#pragma unroll
        for (int e = 0; e < N_EXP; e++) { p[e] = acc[e] + br[e]; mx = fmaxf(mx, p[e]); }
#pragma unroll
        for (int e = 0; e < N_EXP; e++) { p[e] = expf(p[e] - mx); den += p[e]; }
#pragma unroll
        for (int e = 0; e < N_EXP; e++) p[e] /= den;

        int e0 = 0;
#pragma unroll
        for (int e = 1; e < N_EXP; e++) if (p[e] > p[e0]) e0 = e;
        int e1 = (e0 == 0) ? 1 : 0;
#pragma unroll
        for (int e = 0; e < N_EXP; e++) { if (e == e0) continue; if (p[e] > p[e1]) e1 = e; }
        float s = p[e0] + p[e1];

        int i0 = atomicAdd(&g_counts[e0], 1);
        int i1 = atomicAdd(&g_counts[e1], 1);
        g_token_list[e0 * CAP + i0] = t;
        g_token_list[e1 * CAP + i1] = t;
        g_gate_slot[e0 * CAP + i0] = p[e0] / s;
        g_gate_slot[e1 * CAP + i1] = p[e1] / s;
    } else {
        const size_t n4x = (size_t)T_TOK * D_MODEL / 4;
        const size_t n4w = (size_t)N_EXP * D_MODEL * D_FF / 4;
        const size_t n4o = (size_t)T_TOK * D_MODEL / 4;
        const size_t b0 = n4x, b1 = n4x + n4w, b2 = n4x + 2 * n4w;
        const size_t total = b2 + n4o;
        const size_t stride = (size_t)CONV_BLOCKS * 256;
        size_t i = (size_t)(blockIdx.x - ROUTER_BLOCKS) * 256 + threadIdx.x;
        for (; i < total; i += stride) {
            if (i < b0) {
                float4 v = ((const float4*)x)[i];
                ((__half2*)g_xh)[2 * i]     = __floats2half2_rn(v.x, v.y);
                ((__half2*)g_xh)[2 * i + 1] = __floats2half2_rn(v.z, v.w);
            } else if (i < b1) {
                size_t j = i - b0;
                float4 v = ((const float4*)W1)[j];
                ((__half2*)g_w1)[2 * j]     = __floats2half2_rn(v.x, v.y);
                ((__half2*)g_w1)[2 * j + 1] = __floats2half2_rn(v.z, v.w);
            } else if (i < b2) {
                size_t j = i - b1;
                float4 v = ((const float4*)W2)[j];
                ((__half2*)g_w2)[2 * j]     = __floats2half2_rn(v.x, v.y);
                ((__half2*)g_w2)[2 * j + 1] = __floats2half2_rn(v.z, v.w);
            } else {
                ((float4*)out)[i - b2] = make_float4(0.f, 0.f, 0.f, 0.f);
            }
        }
    }
}

// ---------------- GEMM compute step: warp tile 64x64, warp grid 2x2 ------------
__device__ __forceinline__ void compute_stage(uint32_t sb, uint32_t soff,
                                              int wm, int wn, int lane,
                                              float acc[4][8][4]) {
    const uint32_t lrow = lane & 15;
    const uint32_t lhi  = (lane >> 4) << 3;
#pragma unroll
    for (int ks = 0; ks < 2; ks++) {
        uint32_t a[4][4];
#pragma unroll
        for (int mt = 0; mt < 4; mt++) {
            uint32_t addr = sb + soff
                + (uint32_t)(wm * 64 + mt * 16 + lrow) * A_ROW_B
                + (ks * 16 + lhi) * 2;
            ldsm4(a[mt], addr);
        }
        uint32_t b[8][2];
#pragma unroll
        for (int nt2 = 0; nt2 < 4; nt2++) {
            uint32_t addr = sb + soff + OFF_B
                + (uint32_t)(ks * 16 + lrow) * B_ROW_B
                + (uint32_t)(wn * 64 + nt2 * 16 + lhi) * 2;
            uint32_t t[4];
            ldsm4t(t, addr);
            b[nt2 * 2][0] = t[0];     b[nt2 * 2][1] = t[1];
            b[nt2 * 2 + 1][0] = t[2]; b[nt2 * 2 + 1][1] = t[3];
        }
#pragma unroll
        for (int mt = 0; mt < 4; mt++)
#pragma unroll
            for (int nt = 0; nt < 8; nt++)
                mma16816(acc[mt][nt], a[mt], b[nt]);
    }
}

// ---------------- GEMM1: h = relu(x[gather] @ W1[e] + b1[e]) -------------------
__global__ __launch_bounds__(128, 2)
void gemm1_mma(const float* __restrict__ b1) {
    extern __shared__ char smem[];
    const int e = blockIdx.z;
    const int count = g_counts[e];
    const int m0 = blockIdx.y * 128;
    if (m0 >= count) return;
    const int n0 = blockIdx.x * 128;

    const int tid = threadIdx.x;
    const int lane = tid & 31, wid = tid >> 5;
    const int wm = wid >> 1, wn = wid & 1;
    const uint32_t sb = smem_u32(smem);

    int* stok = (int*)(smem + HDR_OFF);
    int* ssz  = (int*)(smem + HDR_OFF + 512);
    {
        int r = m0 + tid;
        bool v = r < count;
        stok[tid] = v ? g_token_list[e * CAP + r] : 0;
        ssz[tid]  = v ? 16 : 0;
    }
    __syncthreads();

    const __half* Bg = g_w1 + (size_t)e * D_MODEL * D_FF;

    auto issue_loads = [&](int stage, int k0) {
#pragma unroll
        for (int h = 0; h < 4; h++) {   // A: 512 cp16
            int idx = tid + h * 128;
            int row = idx >> 2, c4 = idx & 3;
            uint32_t dst = sb + stage * STAGE_B + (uint32_t)row * A_ROW_B + c4 * 16;
            cp16(dst, g_xh + (size_t)stok[row] * D_MODEL + k0 + c4 * 8, ssz[row]);
        }
#pragma unroll
        for (int h = 0; h < 4; h++) {   // B: 512 cp16
            int idx = tid + h * 128;
            int row = idx >> 4, c16 = idx & 15;
            uint32_t dst = sb + stage * STAGE_B + OFF_B
                         + (uint32_t)row * B_ROW_B + c16 * 16;
            cp16(dst, Bg + (size_t)(k0 + row) * D_FF + n0 + c16 * 8, 16);
        }
        cp_commit();
    };

    float acc[4][8][4];
#pragma unroll
    for (int mt = 0; mt < 4; mt++)
#pragma unroll
        for (int nt = 0; nt < 8; nt++)
#pragma unroll
            for (int q = 0; q < 4; q++) acc[mt][nt][q] = 0.f;

    const int NCH = D_MODEL / 32;  // 32
    issue_loads(0, 0);
    issue_loads(1, 32);
    issue_loads(2, 64);

#pragma unroll 1
    for (int i = 0; i < NCH; i++) {
        cp_wait<2>();
        __syncthreads();
        if (i + 3 < NCH) issue_loads((i + 3) & 3, (i + 3) * 32);
        else cp_commit();
        compute_stage(sb, (i & 3) * STAGE_B, wm, wn, lane, acc);
    }

    // epilogue: bias + relu -> fp16 plane
    const int lrow = lane >> 2, lcol = (lane & 3) * 2;
    const float* b1e = b1 + (size_t)e * D_FF + n0 + wn * 64;
    float2 bias[8];
#pragma unroll
    for (int nt = 0; nt < 8; nt++) bias[nt] = *(const float2*)(b1e + nt * 8 + lcol);

#pragma unroll
    for (int mt = 0; mt < 4; mt++)
#pragma unroll
        for (int half = 0; half < 2; half++) {
            int r = m0 + wm * 64 + mt * 16 + lrow + half * 8;
            if (r >= count) continue;
            size_t base = ((size_t)e * CAP + r) * D_FF + n0 + wn * 64;
#pragma unroll
            for (int nt = 0; nt < 8; nt++) {
                float v0 = fmaxf(acc[mt][nt][half * 2 + 0] + bias[nt].x, 0.f);
                float v1 = fmaxf(acc[mt][nt][half * 2 + 1] + bias[nt].y, 0.f);
                *(__half2*)(g_hh + base + nt * 8 + lcol) = __floats2half2_rn(v0, v1);
            }
        }
}

// ---------------- GEMM2 (split-K=2): out[tok] += gate*(h @ W2[e] + b2[e]) ------
__global__ __launch_bounds__(128, 2)
void gemm2_mma(const float* __restrict__ b2, float* __restrict__ out) {
    extern __shared__ char smem[];
    const int e = blockIdx.z >> 1;
    const int split = blockIdx.z & 1;
    const int count = g_counts[e];
    const int m0 = blockIdx.y * 128;
    if (m0 >= count) return;
    const int n0 = blockIdx.x * 128;
    const int kbase = split * (D_FF / 2);

    const int tid = threadIdx.x;
    const int lane = tid & 31, wid = tid >> 5;
    const int wm = wid >> 1, wn = wid & 1;
    const uint32_t sb = smem_u32(smem);

    const __half* Bg = g_w2 + (size_t)e * D_FF * D_MODEL;
    const size_t arow0 = ((size_t)e * CAP + m0) * D_FF + kbase;

    auto issue_loads = [&](int stage, int k0) {
#pragma unroll
        for (int h = 0; h < 4; h++) {
            int idx = tid + h * 128;
            int row = idx >> 2, c4 = idx & 3;
            uint32_t dst = sb + stage * STAGE_B + (uint32_t)row * A_ROW_B + c4 * 16;
            cp16(dst, g_hh + arow0 + (size_t)row * D_FF + k0 + c4 * 8, 16);
        }
#pragma unroll
        for (int h = 0; h < 4; h++) {
            int idx = tid + h * 128;
            int row = idx >> 4, c16 = idx & 15;
            uint32_t dst = sb + stage * STAGE_B + OFF_B
                         + (uint32_t)row * B_ROW_B + c16 * 16;
            cp16(dst, Bg + (size_t)(kbase + k0 + row) * D_MODEL + n0 + c16 * 8, 16);
        }
        cp_commit();
    };

    float acc[4][8][4];
#pragma unroll
    for (int mt = 0; mt < 4; mt++)
#pragma unroll
        for (int nt = 0; nt < 8; nt++)
#pragma unroll
            for (int q = 0; q < 4; q++) acc[mt][nt][q] = 0.f;

    const int NCH = (D_FF / 2) / 32;  // 64
    issue_loads(0, 0);
    issue_loads(1, 32);
    issue_loads(2, 64);

#pragma unroll 1
    for (int i = 0; i < NCH; i++) {
        cp_wait<2>();
        __syncthreads();
        if (i + 3 < NCH) issue_loads((i + 3) & 3, (i + 3) * 32);
        else cp_commit();
        compute_stage(sb, (i & 3) * STAGE_B, wm, wn, lane, acc);
    }

    // epilogue: (bias only from split 0) + gate, commutative atomic combine
    const int lrow = lane >> 2, lcol = (lane & 3) * 2;
    const float* b2e = b2 + (size_t)e * D_MODEL + n0 + wn * 64;
    float2 bias[8];
#pragma unroll
    for (int nt = 0; nt < 8; nt++) {
        if (split == 0) bias[nt] = *(const float2*)(b2e + nt * 8 + lcol);
        else            bias[nt] = make_float2(0.f, 0.f);
    }

#pragma unroll
    for (int mt = 0; mt < 4; mt++)
#pragma unroll
        for (int half = 0; half < 2; half++) {
            int r = m0 + wm * 64 + mt * 16 + lrow + half * 8;
            if (r >= count) continue;
            int tok = g_token_list[e * CAP + r];
            float gate = g_gate_slot[e * CAP + r];
            float* op = out + (size_t)tok * D_MODEL + n0 + wn * 64;
#pragma unroll
            for (int nt = 0; nt < 8; nt++) {
                atomicAdd(op + nt * 8 + lcol + 0, (acc[mt][nt][half * 2 + 0] + bias[nt].x) * gate);
                atomicAdd(op + nt * 8 + lcol + 1, (acc[mt][nt][half * 2 + 1] + bias[nt].y) * gate);
            }
        }
}

// ---------------- launch --------------------------------------------------------
extern "C" void kernel_launch(void* const* d_in, const int* in_sizes, int n_in,
                              void* d_out, int out_size) {
    const float* x  = (const float*)d_in[0];
    const float* Wr = (const float*)d_in[1];
    const float* br = (const float*)d_in[2];
    const float* W1 = (const float*)d_in[3];
    const float* b1 = (const float*)d_in[4];
    const float* W2 = (const float*)d_in[5];
    const float* b2 = (const float*)d_in[6];
    float* out = (float*)d_out;

    cudaFuncSetAttribute(gemm1_mma, cudaFuncAttributeMaxDynamicSharedMemorySize, SMEM_TOTAL);
    cudaFuncSetAttribute(gemm2_mma, cudaFuncAttributeMaxDynamicSharedMemorySize, SMEM_TOTAL);

    zero_counts_kernel<<<1, 32>>>();

    prep_kernel<<<ROUTER_BLOCKS + CONV_BLOCKS, 256>>>(x, Wr, br, W1, W2, out);

    dim3 g1(D_FF / 128, CAP / 128, N_EXP);
    gemm1_mma<<<g1, 128, SMEM_TOTAL>>>(b1);

    dim3 g2(D_MODEL / 128, CAP / 128, N_EXP * 2);
    gemm2_mma<<<g2, 128, SMEM_TOTAL>>>(b2, out);
}

// round 10
// speedup vs baseline: 6.8606x; 1.0113x over previous
#include <cuda_runtime.h>
#include <cuda_fp16.h>
#include <cstdint>
#include <math.h>

#define D_MODEL 1024
#define D_FF    4096
#define N_EXP   8
#define T_TOK   4096
#define CAP     4096

// SMEM stage geometry (bytes) — tile 128x128, BK=32, 4 stages
#define A_ROW_B  80                        // 32 fp16 (64B) + 16B pad
#define A_PLANE  (128 * A_ROW_B)           // 10240
#define B_ROW_B  272                       // 128 fp16 (256B) + 16B pad
#define B_PLANE  (32 * B_ROW_B)            // 8704
#define OFF_B    A_PLANE
#define STAGE_B  (A_PLANE + B_PLANE)       // 18944
#define NSTAGE   4
#define HDR_OFF  (NSTAGE * STAGE_B)        // 75776
#define SMEM_TOTAL (HDR_OFF + 1024)        // 76800  (2 CTAs/SM: 153.6 KB)

#define ROUTER_BLOCKS (T_TOK / 8)          // 512
#define CONV_BLOCKS   4096
#define W2CVT_BLOCKS  1024                 // extra z-plane blocks inside gemm1

// ---------------- scratch (device globals; zero-initialized) ----------------
__device__ int    g_counts[N_EXP];
__device__ int    g_token_list[N_EXP * CAP];
__device__ float  g_gate_slot[N_EXP * CAP];
__device__ __half g_xh[(size_t)T_TOK * D_MODEL];
__device__ __half g_w1[(size_t)N_EXP * D_MODEL * D_FF];
__device__ __half g_w2[(size_t)N_EXP * D_FF * D_MODEL];
__device__ __half g_hh[(size_t)N_EXP * CAP * D_FF];   // rows >= count stay 0

// ---------------- PTX helpers ------------------------------------------------
__device__ __forceinline__ uint32_t smem_u32(const void* p) {
    uint32_t a;
    asm("{ .reg .u64 t; cvta.to.shared.u64 t, %1; cvt.u32.u64 %0, t; }" : "=r"(a) : "l"(p));
    return a;
}
__device__ __forceinline__ void cp16(uint32_t dst, const void* src, int szr) {
    asm volatile("cp.async.cg.shared.global [%0], [%1], 16, %2;"
                 :: "r"(dst), "l"(src), "r"(szr) : "memory");
}
__device__ __forceinline__ void cp_commit() {
    asm volatile("cp.async.commit_group;" ::: "memory");
}
template <int N>
__device__ __forceinline__ void cp_wait() {
    asm volatile("cp.async.wait_group %0;" :: "n"(N) : "memory");
}
__device__ __forceinline__ void ldsm4(uint32_t* r, uint32_t addr) {
    asm volatile("ldmatrix.sync.aligned.m8n8.x4.shared.b16 {%0,%1,%2,%3}, [%4];"
                 : "=r"(r[0]), "=r"(r[1]), "=r"(r[2]), "=r"(r[3]) : "r"(addr));
}
__device__ __forceinline__ void ldsm4t(uint32_t* r, uint32_t addr) {
    asm volatile("ldmatrix.sync.aligned.m8n8.x4.trans.shared.b16 {%0,%1,%2,%3}, [%4];"
                 : "=r"(r[0]), "=r"(r[1]), "=r"(r[2]), "=r"(r[3]) : "r"(addr));
}
__device__ __forceinline__ void mma16816(float* c, const uint32_t* a, const uint32_t* b) {
    asm volatile(
        "mma.sync.aligned.m16n8k16.row.col.f32.f16.f16.f32 "
        "{%0,%1,%2,%3}, {%4,%5,%6,%7}, {%8,%9}, {%0,%1,%2,%3};"
        : "+f"(c[0]), "+f"(c[1]), "+f"(c[2]), "+f"(c[3])
        : "r"(a[0]), "r"(a[1]), "r"(a[2]), "r"(a[3]), "r"(b[0]), "r"(b[1]));
}

// ---------------- small kernels -----------------------------------------------
__global__ void zero_counts_kernel() {
    if (threadIdx.x < N_EXP) g_counts[threadIdx.x] = 0;
}

// ---------------- fused prep: router + x/W1 conversions + out zeroing ----------
__global__ __launch_bounds__(256)
void prep_kernel(const float* __restrict__ x, const float* __restrict__ Wr,
                 const float* __restrict__ br, const float* __restrict__ W1,
                 float* __restrict__ out) {
    if (blockIdx.x < ROUTER_BLOCKS) {
        const int tid = threadIdx.x;
        const int lane = tid & 31;
        const int t = blockIdx.x * 8 + (tid >> 5);

        float acc[N_EXP];
#pragma unroll
        for (int e = 0; e < N_EXP; e++) acc[e] = 0.f;
        const float* xr = x + (size_t)t * D_MODEL;
        for (int d = lane; d < D_MODEL; d += 32) {
            float xv = xr[d];
            const float* w = Wr + (size_t)d * N_EXP;
#pragma unroll
            for (int e = 0; e < N_EXP; e++) acc[e] += xv * w[e];
        }
#pragma unroll
        for (int off = 16; off > 0; off >>= 1)
#pragma unroll
            for (int e = 0; e < N_EXP; e++)
                acc[e] += __shfl_down_sync(0xffffffffu, acc[e], off);
        if (lane != 0) return;

        float p[N_EXP], mx = -1e30f, den = 0.f;
#pragma unroll
        for (int e = 0; e < N_EXP; e++) { p[e] = acc[e] + br[e]; mx = fmaxf(mx, p[e]); }
#pragma unroll
        for (int e = 0; e < N_EXP; e++) { p[e] = expf(p[e] - mx); den += p[e]; }
#pragma unroll
        for (int e = 0; e < N_EXP; e++) p[e] /= den;

        int e0 = 0;
#pragma unroll
        for (int e = 1; e < N_EXP; e++) if (p[e] > p[e0]) e0 = e;
        int e1 = (e0 == 0) ? 1 : 0;
#pragma unroll
        for (int e = 0; e < N_EXP; e++) { if (e == e0) continue; if (p[e] > p[e1]) e1 = e; }
        float s = p[e0] + p[e1];

        int i0 = atomicAdd(&g_counts[e0], 1);
        int i1 = atomicAdd(&g_counts[e1], 1);
        g_token_list[e0 * CAP + i0] = t;
        g_token_list[e1 * CAP + i1] = t;
        g_gate_slot[e0 * CAP + i0] = p[e0] / s;
        g_gate_slot[e1 * CAP + i1] = p[e1] / s;
    } else {
        // x -> fp16, W1 -> fp16, out = 0 (grid-strided float4 items)
        const size_t n4x = (size_t)T_TOK * D_MODEL / 4;
        const size_t n4w = (size_t)N_EXP * D_MODEL * D_FF / 4;
        const size_t n4o = (size_t)T_TOK * D_MODEL / 4;
        const size_t b0 = n4x, b1 = n4x + n4w;
        const size_t total = b1 + n4o;
        const size_t stride = (size_t)CONV_BLOCKS * 256;
        size_t i = (size_t)(blockIdx.x - ROUTER_BLOCKS) * 256 + threadIdx.x;
        for (; i < total; i += stride) {
            if (i < b0) {
                float4 v = ((const float4*)x)[i];
                ((__half2*)g_xh)[2 * i]     = __floats2half2_rn(v.x, v.y);
                ((__half2*)g_xh)[2 * i + 1] = __floats2half2_rn(v.z, v.w);
            } else if (i < b1) {
                size_t j = i - b0;
                float4 v = ((const float4*)W1)[j];
                ((__half2*)g_w1)[2 * j]     = __floats2half2_rn(v.x, v.y);
                ((__half2*)g_w1)[2 * j + 1] = __floats2half2_rn(v.z, v.w);
            } else {
                ((float4*)out)[i - b1] = make_float4(0.f, 0.f, 0.f, 0.f);
            }
        }
    }
}

// ---------------- GEMM compute step: warp tile 64x64, warp grid 2x2 ------------
__device__ __forceinline__ void compute_stage(uint32_t sb, uint32_t soff,
                                              int wm, int wn, int lane,
                                              float acc[4][8][4]) {
    const uint32_t lrow = lane & 15;
    const uint32_t lhi  = (lane >> 4) << 3;
#pragma unroll
    for (int ks = 0; ks < 2; ks++) {
        uint32_t a[4][4];
#pragma unroll
        for (int mt = 0; mt < 4; mt++) {
            uint32_t addr = sb + soff
                + (uint32_t)(wm * 64 + mt * 16 + lrow) * A_ROW_B
                + (ks * 16 + lhi) * 2;
            ldsm4(a[mt], addr);
        }
        uint32_t b[8][2];
#pragma unroll
        for (int nt2 = 0; nt2 < 4; nt2++) {
            uint32_t addr = sb + soff + OFF_B
                + (uint32_t)(ks * 16 + lrow) * B_ROW_B
                + (uint32_t)(wn * 64 + nt2 * 16 + lhi) * 2;
            uint32_t t[4];
            ldsm4t(t, addr);
            b[nt2 * 2][0] = t[0];     b[nt2 * 2][1] = t[1];
            b[nt2 * 2 + 1][0] = t[2]; b[nt2 * 2 + 1][1] = t[3];
        }
#pragma unroll
        for (int mt = 0; mt < 4; mt++)
#pragma unroll
            for (int nt = 0; nt < 8; nt++)
                mma16816(acc[mt][nt], a[mt], b[nt]);
    }
}

// ---------------- GEMM1 (+ hidden W2 conversion plane) -------------------------
__global__ __launch_bounds__(128, 2)
void gemm1_mma(const float* __restrict__ b1, const float* __restrict__ W2) {
    // extra z-plane: convert W2 -> fp16 concurrently with gemm1 compute
    if (blockIdx.z == N_EXP) {
        const size_t n4w = (size_t)N_EXP * D_FF * D_MODEL / 4;
        const size_t stride = (size_t)W2CVT_BLOCKS * 128;
        size_t i = (size_t)(blockIdx.y * gridDim.x + blockIdx.x) * 128 + threadIdx.x;
        for (; i < n4w; i += stride) {
            float4 v = ((const float4*)W2)[i];
            ((__half2*)g_w2)[2 * i]     = __floats2half2_rn(v.x, v.y);
            ((__half2*)g_w2)[2 * i + 1] = __floats2half2_rn(v.z, v.w);
        }
        return;
    }

    extern __shared__ char smem[];
    const int e = blockIdx.z;
    const int count = g_counts[e];
    const int m0 = blockIdx.y * 128;
    if (m0 >= count) return;
    const int n0 = blockIdx.x * 128;

    const int tid = threadIdx.x;
    const int lane = tid & 31, wid = tid >> 5;
    const int wm = wid >> 1, wn = wid & 1;
    const uint32_t sb = smem_u32(smem);

    int* stok = (int*)(smem + HDR_OFF);
    int* ssz  = (int*)(smem + HDR_OFF + 512);
    {
        int r = m0 + tid;
        bool v = r < count;
        stok[tid] = v ? g_token_list[e * CAP + r] : 0;
        ssz[tid]  = v ? 16 : 0;
    }
    __syncthreads();

    const __half* Bg = g_w1 + (size_t)e * D_MODEL * D_FF;

    auto issue_loads = [&](int stage, int k0) {
#pragma unroll
        for (int h = 0; h < 4; h++) {   // A: 512 cp16
            int idx = tid + h * 128;
            int row = idx >> 2, c4 = idx & 3;
            uint32_t dst = sb + stage * STAGE_B + (uint32_t)row * A_ROW_B + c4 * 16;
            cp16(dst, g_xh + (size_t)stok[row] * D_MODEL + k0 + c4 * 8, ssz[row]);
        }
#pragma unroll
        for (int h = 0; h < 4; h++) {   // B: 512 cp16
            int idx = tid + h * 128;
            int row = idx >> 4, c16 = idx & 15;
            uint32_t dst = sb + stage * STAGE_B + OFF_B
                         + (uint32_t)row * B_ROW_B + c16 * 16;
            cp16(dst, Bg + (size_t)(k0 + row) * D_FF + n0 + c16 * 8, 16);
        }
        cp_commit();
    };

    float acc[4][8][4];
#pragma unroll
    for (int mt = 0; mt < 4; mt++)
#pragma unroll
        for (int nt = 0; nt < 8; nt++)
#pragma unroll
            for (int q = 0; q < 4; q++) acc[mt][nt][q] = 0.f;

    const int NCH = D_MODEL / 32;  // 32
    issue_loads(0, 0);
    issue_loads(1, 32);
    issue_loads(2, 64);

#pragma unroll 1
    for (int i = 0; i < NCH; i++) {
        cp_wait<2>();
        __syncthreads();
        if (i + 3 < NCH) issue_loads((i + 3) & 3, (i + 3) * 32);
        else cp_commit();
        compute_stage(sb, (i & 3) * STAGE_B, wm, wn, lane, acc);
    }

    // epilogue: bias + relu -> fp16 plane
    const int lrow = lane >> 2, lcol = (lane & 3) * 2;
    const float* b1e = b1 + (size_t)e * D_FF + n0 + wn * 64;
    float2 bias[8];
#pragma unroll
    for (int nt = 0; nt < 8; nt++) bias[nt] = *(const float2*)(b1e + nt * 8 + lcol);

#pragma unroll
    for (int mt = 0; mt < 4; mt++)
#pragma unroll
        for (int half = 0; half < 2; half++) {
            int r = m0 + wm * 64 + mt * 16 + lrow + half * 8;
            if (r >= count) continue;
            size_t base = ((size_t)e * CAP + r) * D_FF + n0 + wn * 64;
#pragma unroll
            for (int nt = 0; nt < 8; nt++) {
                float v0 = fmaxf(acc[mt][nt][half * 2 + 0] + bias[nt].x, 0.f);
                float v1 = fmaxf(acc[mt][nt][half * 2 + 1] + bias[nt].y, 0.f);
                *(__half2*)(g_hh + base + nt * 8 + lcol) = __floats2half2_rn(v0, v1);
            }
        }
}

// ---------------- GEMM2 (split-K=2): out[tok] += gate*(h @ W2[e] + b2[e]) ------
__global__ __launch_bounds__(128, 2)
void gemm2_mma(const float* __restrict__ b2, float* __restrict__ out) {
    extern __shared__ char smem[];
    const int e = blockIdx.z >> 1;
    const int split = blockIdx.z & 1;
    const int count = g_counts[e];
    const int m0 = blockIdx.y * 128;
    if (m0 >= count) return;
    const int n0 = blockIdx.x * 128;
    const int kbase = split * (D_FF / 2);

    const int tid = threadIdx.x;
    const int lane = tid & 31, wid = tid >> 5;
    const int wm = wid >> 1, wn = wid & 1;
    const uint32_t sb = smem_u32(smem);

    const __half* Bg = g_w2 + (size_t)e * D_FF * D_MODEL;
    const size_t arow0 = ((size_t)e * CAP + m0) * D_FF + kbase;

    auto issue_loads = [&](int stage, int k0) {
#pragma unroll
        for (int h = 0; h < 4; h++) {
            int idx = tid + h * 128;
            int row = idx >> 2, c4 = idx & 3;
            uint32_t dst = sb + stage * STAGE_B + (uint32_t)row * A_ROW_B + c4 * 16;
            cp16(dst, g_hh + arow0 + (size_t)row * D_FF + k0 + c4 * 8, 16);
        }
#pragma unroll
        for (int h = 0; h < 4; h++) {
            int idx = tid + h * 128;
            int row = idx >> 4, c16 = idx & 15;
            uint32_t dst = sb + stage * STAGE_B + OFF_B
                         + (uint32_t)row * B_ROW_B + c16 * 16;
            cp16(dst, Bg + (size_t)(kbase + k0 + row) * D_MODEL + n0 + c16 * 8, 16);
        }
        cp_commit();
    };

    float acc[4][8][4];
#pragma unroll
    for (int mt = 0; mt < 4; mt++)
#pragma unroll
        for (int nt = 0; nt < 8; nt++)
#pragma unroll
            for (int q = 0; q < 4; q++) acc[mt][nt][q] = 0.f;

    const int NCH = (D_FF / 2) / 32;  // 64
    issue_loads(0, 0);
    issue_loads(1, 32);
    issue_loads(2, 64);

#pragma unroll 1
    for (int i = 0; i < NCH; i++) {
        cp_wait<2>();
        __syncthreads();
        if (i + 3 < NCH) issue_loads((i + 3) & 3, (i + 3) * 32);
        else cp_commit();
        compute_stage(sb, (i & 3) * STAGE_B, wm, wn, lane, acc);
    }

    // epilogue: (bias only from split 0) + gate, commutative atomic combine
    const int lrow = lane >> 2, lcol = (lane & 3) * 2;
    const float* b2e = b2 + (size_t)e * D_MODEL + n0 + wn * 64;
    float2 bias[8];
#pragma unroll
    for (int nt = 0; nt < 8; nt++) {
        if (split == 0) bias[nt] = *(const float2*)(b2e + nt * 8 + lcol);
        else            bias[nt] = make_float2(0.f, 0.f);
    }

#pragma unroll
    for (int mt = 0; mt < 4; mt++)
#pragma unroll
        for (int half = 0; half < 2; half++) {
            int r = m0 + wm * 64 + mt * 16 + lrow + half * 8;
            if (r >= count) continue;
            int tok = g_token_list[e * CAP + r];
            float gate = g_gate_slot[e * CAP + r];
            float* op = out + (size_t)tok * D_MODEL + n0 + wn * 64;
#pragma unroll
            for (int nt = 0; nt < 8; nt++) {
                atomicAdd(op + nt * 8 + lcol + 0, (acc[mt][nt][half * 2 + 0] + bias[nt].x) * gate);
                atomicAdd(op + nt * 8 + lcol + 1, (acc[mt][nt][half * 2 + 1] + bias[nt].y) * gate);
            }
        }
}

// ---------------- launch --------------------------------------------------------
extern "C" void kernel_launch(void* const* d_in, const int* in_sizes, int n_in,
                              void* d_out, int out_size) {
    const float* x  = (const float*)d_in[0];
    const float* Wr = (const float*)d_in[1];
    const float* br = (const float*)d_in[2];
    const float* W1 = (const float*)d_in[3];
    const float* b1 = (const float*)d_in[4];
    const float* W2 = (const float*)d_in[5];
    const float* b2 = (const float*)d_in[6];
    float* out = (float*)d_out;

    cudaFuncSetAttribute(gemm1_mma, cudaFuncAttributeMaxDynamicSharedMemorySize, SMEM_TOTAL);
    cudaFuncSetAttribute(gemm2_mma, cudaFuncAttributeMaxDynamicSharedMemorySize, SMEM_TOTAL);

    zero_counts_kernel<<<1, 32>>>();

    // prep: router + x/W1 fp16 conversion + out zeroing
    prep_kernel<<<ROUTER_BLOCKS + CONV_BLOCKS, 256>>>(x, Wr, br, W1, out);

    // gemm1 + hidden W2 conversion plane (z == N_EXP)
    dim3 g1(D_FF / 128, CAP / 128, N_EXP + 1);
    gemm1_mma<<<g1, 128, SMEM_TOTAL>>>(b1, W2);

    dim3 g2(D_MODEL / 128, CAP / 128, N_EXP * 2);
    gemm2_mma<<<g2, 128, SMEM_TOTAL>>>(b2, out);
}